// round 1
// baseline (speedup 1.0000x reference)
#include <cuda_runtime.h>

#define BB 2
#define LL 2048
#define DM 1024
#define NH 16
#define DK 64
#define MROWS (BB * LL)   // 4096

// Scratch (no allocations allowed): 4 x 16MB fp32
__device__ float g_qh[NH * MROWS * DK];   // [h][b*L+l][k]
__device__ float g_kh[NH * MROWS * DK];
__device__ float g_vh[NH * MROWS * DK];
__device__ float g_att[MROWS * DM];       // [b*L+l][h*64+k]

// ---------------------------------------------------------------------------
// Kernel 1: per-head input projections.
// C[64x64] tile = X[row0..row0+64, 0:1024] @ w[h][0:1024, 0:64]
// grid: (MROWS/64, NH, 3) ; block 256 ; each thread 4x4 micro-tile.
// ---------------------------------------------------------------------------
__global__ __launch_bounds__(256) void proj_kernel(
    const float* __restrict__ qin, const float* __restrict__ kin,
    const float* __restrict__ vin,
    const float* __restrict__ wq, const float* __restrict__ wk,
    const float* __restrict__ wv)
{
    const float* X; const float* W; float* O;
    if (blockIdx.z == 0)      { X = qin; W = wq; O = g_qh; }
    else if (blockIdx.z == 1) { X = kin; W = wk; O = g_kh; }
    else                      { X = vin; W = wv; O = g_vh; }

    const int h    = blockIdx.y;
    const int row0 = blockIdx.x * 64;
    W += (size_t)h * DM * DK;   // [1024][64] row-major slice for this head

    __shared__ float Ast[16][68];  // A tile transposed: [k][row], padded
    __shared__ float Bs[16][64];   // W tile: [k][col]

    const int t  = threadIdx.x;
    const int tx = t & 15, ty = t >> 4;
    const int ra = t >> 2, ca = (t & 3) * 4;    // A-tile load coords
    const int rb = t >> 4, cb = (t & 15) * 4;   // B-tile load coords

    float acc[4][4] = {};

    for (int k0 = 0; k0 < DM; k0 += 16) {
        float4 a = *(const float4*)(X + (size_t)(row0 + ra) * DM + (k0 + ca));
        float4 w = *(const float4*)(W + (size_t)(k0 + rb) * DK + cb);
        Ast[ca + 0][ra] = a.x; Ast[ca + 1][ra] = a.y;
        Ast[ca + 2][ra] = a.z; Ast[ca + 3][ra] = a.w;
        *(float4*)&Bs[rb][cb] = w;
        __syncthreads();
        #pragma unroll
        for (int kk = 0; kk < 16; ++kk) {
            float4 av = *(const float4*)&Ast[kk][ty * 4];
            float4 bv = *(const float4*)&Bs[kk][tx * 4];
            const float aa[4] = {av.x, av.y, av.z, av.w};
            const float bb[4] = {bv.x, bv.y, bv.z, bv.w};
            #pragma unroll
            for (int i = 0; i < 4; ++i)
                #pragma unroll
                for (int j = 0; j < 4; ++j)
                    acc[i][j] = fmaf(aa[i], bb[j], acc[i][j]);
        }
        __syncthreads();
    }

    float* Oh = O + (size_t)h * MROWS * DK;
    #pragma unroll
    for (int i = 0; i < 4; ++i)
        #pragma unroll
        for (int j = 0; j < 4; ++j)
            Oh[(size_t)(row0 + ty * 4 + i) * DK + tx * 4 + j] = acc[i][j];
}

// ---------------------------------------------------------------------------
// Kernel 2: flash-style attention per (h,b), 64 query rows per block.
// S = Qtile @ Ktile^T (fp32), online softmax, O += P @ Vtile,
// epilogue: O = (acc/l) * qh, stored concat-layout into g_att.
// grid: (LL/64, NH*BB) ; block 256 ; dynamic smem 67584 B.
// ---------------------------------------------------------------------------
#define ATTN_SMEM ((2 * 64 * 68 + 2 * 64 * 64) * 4)

__global__ __launch_bounds__(256) void attn_kernel()
{
    extern __shared__ float sm[];
    float* Qt = sm;                 // [64 k][68] transposed Q tile
    float* Kt = sm + 64 * 68;       // [64 k][68] transposed K tile
    float* Vs = sm + 2 * 64 * 68;   // [64 j][64 d] natural V tile
    float* Ps = Vs + 64 * 64;       // [64 i][64 j] probabilities

    const int hb = blockIdx.y;        // h*BB + b
    const int h  = hb >> 1, b = hb & 1;
    const int l0 = blockIdx.x * 64;
    const float* qh = g_qh + (size_t)hb * LL * DK;
    const float* kh = g_kh + (size_t)hb * LL * DK;
    const float* vh = g_vh + (size_t)hb * LL * DK;

    const int t  = threadIdx.x;
    const int tx = t & 15, ty = t >> 4;

    // Load Q tile once, transposed into Qt[k][i]
    #pragma unroll
    for (int it = 0; it < 4; ++it) {
        int idx = it * 256 + t;
        int r = idx >> 4;            // 0..63 local row
        int c = (idx & 15) * 4;      // 0..60 dk
        float4 a = *(const float4*)(qh + (size_t)(l0 + r) * DK + c);
        Qt[(c + 0) * 68 + r] = a.x; Qt[(c + 1) * 68 + r] = a.y;
        Qt[(c + 2) * 68 + r] = a.z; Qt[(c + 3) * 68 + r] = a.w;
    }

    float acc[4][4] = {};
    float mrow[4] = {-1e30f, -1e30f, -1e30f, -1e30f};
    float lrow[4] = {};

    for (int j0 = 0; j0 < LL; j0 += 64) {
        __syncthreads();   // prior iteration's reads of Kt/Vs/Ps done
        #pragma unroll
        for (int it = 0; it < 4; ++it) {
            int idx = it * 256 + t;
            int r = idx >> 4;
            int c = (idx & 15) * 4;
            float4 kv = *(const float4*)(kh + (size_t)(j0 + r) * DK + c);
            Kt[(c + 0) * 68 + r] = kv.x; Kt[(c + 1) * 68 + r] = kv.y;
            Kt[(c + 2) * 68 + r] = kv.z; Kt[(c + 3) * 68 + r] = kv.w;
            *(float4*)&Vs[r * 64 + c] =
                *(const float4*)(vh + (size_t)(j0 + r) * DK + c);
        }
        __syncthreads();

        // S[i][j] = sum_k Q[i][k] * K[j][k]
        float s[4][4] = {};
        #pragma unroll 16
        for (int kk = 0; kk < 64; ++kk) {
            float4 av = *(const float4*)&Qt[kk * 68 + ty * 4];
            float4 bv = *(const float4*)&Kt[kk * 68 + tx * 4];
            const float aa[4] = {av.x, av.y, av.z, av.w};
            const float bb[4] = {bv.x, bv.y, bv.z, bv.w};
            #pragma unroll
            for (int i = 0; i < 4; ++i)
                #pragma unroll
                for (int j = 0; j < 4; ++j)
                    s[i][j] = fmaf(aa[i], bb[j], s[i][j]);
        }

        // online softmax: row reductions across the 16 tx lanes (half-warp)
        float mloc[4], rsum[4], scl[4];
        #pragma unroll
        for (int i = 0; i < 4; ++i)
            mloc[i] = fmaxf(fmaxf(s[i][0], s[i][1]), fmaxf(s[i][2], s[i][3]));
        #pragma unroll
        for (int off = 8; off > 0; off >>= 1)
            #pragma unroll
            for (int i = 0; i < 4; ++i)
                mloc[i] = fmaxf(mloc[i], __shfl_xor_sync(0xffffffffu, mloc[i], off));

        float p[4][4];
        #pragma unroll
        for (int i = 0; i < 4; ++i) {
            float mnew = fmaxf(mrow[i], mloc[i]);
            scl[i] = __expf(mrow[i] - mnew);
            mrow[i] = mnew;
            float rs = 0.f;
            #pragma unroll
            for (int j = 0; j < 4; ++j) {
                p[i][j] = __expf(s[i][j] - mnew);
                rs += p[i][j];
            }
            rsum[i] = rs;
        }
        #pragma unroll
        for (int off = 8; off > 0; off >>= 1)
            #pragma unroll
            for (int i = 0; i < 4; ++i)
                rsum[i] += __shfl_xor_sync(0xffffffffu, rsum[i], off);
        #pragma unroll
        for (int i = 0; i < 4; ++i) {
            lrow[i] = lrow[i] * scl[i] + rsum[i];
            #pragma unroll
            for (int j = 0; j < 4; ++j) acc[i][j] *= scl[i];
        }
        #pragma unroll
        for (int i = 0; i < 4; ++i)
            *(float4*)&Ps[(ty * 4 + i) * 64 + tx * 4] =
                make_float4(p[i][0], p[i][1], p[i][2], p[i][3]);
        __syncthreads();

        // acc[i][d] += sum_j P[i][j] * V[j][d]
        #pragma unroll 16
        for (int j = 0; j < 64; ++j) {
            float4 vv = *(const float4*)&Vs[j * 64 + tx * 4];
            float p0 = Ps[(ty * 4 + 0) * 64 + j];
            float p1 = Ps[(ty * 4 + 1) * 64 + j];
            float p2 = Ps[(ty * 4 + 2) * 64 + j];
            float p3 = Ps[(ty * 4 + 3) * 64 + j];
            acc[0][0] = fmaf(p0, vv.x, acc[0][0]); acc[0][1] = fmaf(p0, vv.y, acc[0][1]);
            acc[0][2] = fmaf(p0, vv.z, acc[0][2]); acc[0][3] = fmaf(p0, vv.w, acc[0][3]);
            acc[1][0] = fmaf(p1, vv.x, acc[1][0]); acc[1][1] = fmaf(p1, vv.y, acc[1][1]);
            acc[1][2] = fmaf(p1, vv.z, acc[1][2]); acc[1][3] = fmaf(p1, vv.w, acc[1][3]);
            acc[2][0] = fmaf(p2, vv.x, acc[2][0]); acc[2][1] = fmaf(p2, vv.y, acc[2][1]);
            acc[2][2] = fmaf(p2, vv.z, acc[2][2]); acc[2][3] = fmaf(p2, vv.w, acc[2][3]);
            acc[3][0] = fmaf(p3, vv.x, acc[3][0]); acc[3][1] = fmaf(p3, vv.y, acc[3][1]);
            acc[3][2] = fmaf(p3, vv.z, acc[3][2]); acc[3][3] = fmaf(p3, vv.w, acc[3][3]);
        }
    }

    // Epilogue: (acc / l) * qh, store concat layout [b*L+l][h*64+d]
    #pragma unroll
    for (int i = 0; i < 4; ++i) {
        const int li = ty * 4 + i;
        const float inv = 1.0f / lrow[i];
        #pragma unroll
        for (int j = 0; j < 4; ++j) {
            const int d = tx * 4 + j;
            const float qv = Qt[d * 68 + li];
            g_att[(size_t)(b * LL + l0 + li) * DM + h * DK + d] =
                acc[i][j] * inv * qv;
        }
    }
}

// ---------------------------------------------------------------------------
// Kernel 3: Y = g_att @ w_proj^T + b  (NT GEMM, 4096x1024x1024)
// grid: (MROWS/64, DM/64) ; block 256.
// ---------------------------------------------------------------------------
__global__ __launch_bounds__(256) void outproj_kernel(
    const float* __restrict__ wp, const float* __restrict__ bias,
    float* __restrict__ out)
{
    const int row0 = blockIdx.x * 64;
    const int col0 = blockIdx.y * 64;

    __shared__ float Ast[16][68];
    __shared__ float Bst[16][68];

    const int t  = threadIdx.x;
    const int tx = t & 15, ty = t >> 4;
    const int ra = t >> 2, ca = (t & 3) * 4;

    float acc[4][4] = {};

    for (int k0 = 0; k0 < DM; k0 += 16) {
        float4 a = *(const float4*)(g_att + (size_t)(row0 + ra) * DM + k0 + ca);
        float4 w = *(const float4*)(wp + (size_t)(col0 + ra) * DM + k0 + ca);
        Ast[ca + 0][ra] = a.x; Ast[ca + 1][ra] = a.y;
        Ast[ca + 2][ra] = a.z; Ast[ca + 3][ra] = a.w;
        Bst[ca + 0][ra] = w.x; Bst[ca + 1][ra] = w.y;
        Bst[ca + 2][ra] = w.z; Bst[ca + 3][ra] = w.w;
        __syncthreads();
        #pragma unroll
        for (int kk = 0; kk < 16; ++kk) {
            float4 av = *(const float4*)&Ast[kk][ty * 4];
            float4 bv = *(const float4*)&Bst[kk][tx * 4];
            const float aa[4] = {av.x, av.y, av.z, av.w};
            const float bb[4] = {bv.x, bv.y, bv.z, bv.w};
            #pragma unroll
            for (int i = 0; i < 4; ++i)
                #pragma unroll
                for (int j = 0; j < 4; ++j)
                    acc[i][j] = fmaf(aa[i], bb[j], acc[i][j]);
        }
        __syncthreads();
    }

    #pragma unroll
    for (int i = 0; i < 4; ++i)
        #pragma unroll
        for (int j = 0; j < 4; ++j)
            out[(size_t)(row0 + ty * 4 + i) * DM + col0 + tx * 4 + j] =
                acc[i][j] + bias[col0 + tx * 4 + j];
}

// ---------------------------------------------------------------------------
extern "C" void kernel_launch(void* const* d_in, const int* in_sizes, int n_in,
                              void* d_out, int out_size)
{
    const float* q  = (const float*)d_in[0];
    const float* k  = (const float*)d_in[1];
    const float* v  = (const float*)d_in[2];
    const float* wq = (const float*)d_in[3];
    const float* wk = (const float*)d_in[4];
    const float* wv = (const float*)d_in[5];
    const float* wp = (const float*)d_in[6];
    const float* bp = (const float*)d_in[7];
    float* out = (float*)d_out;

    cudaFuncSetAttribute(attn_kernel,
                         cudaFuncAttributeMaxDynamicSharedMemorySize, ATTN_SMEM);

    proj_kernel<<<dim3(MROWS / 64, NH, 3), 256>>>(q, k, v, wq, wk, wv);
    attn_kernel<<<dim3(LL / 64, NH * BB), 256, ATTN_SMEM>>>();
    outproj_kernel<<<dim3(MROWS / 64, DM / 64), 256>>>(wp, bp, out);
}

// round 2
// speedup vs baseline: 1.0627x; 1.0627x over previous
#include <cuda_runtime.h>

#define BB 2
#define LL 2048
#define DM 1024
#define NH 16
#define DK 64
#define MROWS (BB * LL)   // 4096
#define KT 32

typedef unsigned long long u64;

__device__ __forceinline__ u64 pack2(float lo, float hi) {
    u64 r; asm("mov.b64 %0, {%1, %2};" : "=l"(r) : "f"(lo), "f"(hi)); return r;
}
__device__ __forceinline__ void fma2(u64& d, u64 a, u64 b) {
    asm("fma.rn.f32x2 %0, %1, %2, %0;" : "+l"(d) : "l"(a), "l"(b));
}
__device__ __forceinline__ float2 unpack2(u64 v) {
    float lo, hi; asm("mov.b64 {%0, %1}, %2;" : "=f"(lo), "=f"(hi) : "l"(v));
    return make_float2(lo, hi);
}
__device__ __forceinline__ u64 mul2(u64 a, u64 b) {
    u64 r; asm("mul.rn.f32x2 %0, %1, %2;" : "=l"(r) : "l"(a), "l"(b)); return r;
}

// Scratch (no allocations allowed)
__device__ float g_qh[NH * MROWS * DK];   // [h][b*L+l][k]
__device__ float g_kh[NH * MROWS * DK];
__device__ float g_vh[NH * MROWS * DK];
__device__ float g_att[MROWS * DM];       // [b*L+l][h*64+d]

// ---------------------------------------------------------------------------
// Kernel 1: input projections. Block = 128 rows x 128 cols (2 heads) x K=1024.
// grid (32, 8, 3), 256 threads, 8x8 micro-tile (row-pair f32x2 accumulators).
// ---------------------------------------------------------------------------
__global__ __launch_bounds__(256, 2) void proj_kernel(
    const float* __restrict__ qin, const float* __restrict__ kin,
    const float* __restrict__ vin,
    const float* __restrict__ wq, const float* __restrict__ wk,
    const float* __restrict__ wv)
{
    const float* X; const float* W; float* O;
    if (blockIdx.z == 0)      { X = qin; W = wq; O = g_qh; }
    else if (blockIdx.z == 1) { X = kin; W = wk; O = g_kh; }
    else                      { X = vin; W = wv; O = g_vh; }

    const int hp   = blockIdx.y;          // head pair
    const int row0 = blockIdx.x * 128;
    const float* Wh = W + (size_t)(2 * hp) * DM * DK;

    __shared__ float Ast[KT][132];   // A transposed [k][row]
    __shared__ float Bs[KT][128];    // W tile [k][col(2 heads)]

    const int t  = threadIdx.x;
    const int tx = t & 15, ty = t >> 4;

    u64 acc[4][8] = {};   // [row-pair][col] ; rows ty*8+2ip(+1), cols tx*8+j

    for (int k0 = 0; k0 < DM; k0 += KT) {
        float4 ar[4], br[4];
        #pragma unroll
        for (int i = 0; i < 4; ++i) {
            int f = i * 256 + t;
            int arow = f >> 3, akc = (f & 7) * 4;
            ar[i] = *(const float4*)(X + (size_t)(row0 + arow) * DM + k0 + akc);
            int bk = f >> 5, bc = (f & 31) * 4;
            const float* wsrc = Wh + (size_t)(bc >> 6) * DM * DK
                                   + (size_t)(k0 + bk) * DK + (bc & 63);
            br[i] = *(const float4*)wsrc;
        }
        __syncthreads();
        #pragma unroll
        for (int i = 0; i < 4; ++i) {
            int f = i * 256 + t;
            int arow = f >> 3, akc = (f & 7) * 4;
            Ast[akc + 0][arow] = ar[i].x; Ast[akc + 1][arow] = ar[i].y;
            Ast[akc + 2][arow] = ar[i].z; Ast[akc + 3][arow] = ar[i].w;
            int bk = f >> 5, bc = (f & 31) * 4;
            *(float4*)&Bs[bk][bc] = br[i];
        }
        __syncthreads();

        #pragma unroll 4
        for (int kk = 0; kk < KT; ++kk) {
            float4 a0 = *(const float4*)&Ast[kk][ty * 8];
            float4 a1 = *(const float4*)&Ast[kk][ty * 8 + 4];
            float4 b0 = *(const float4*)&Bs[kk][tx * 8];
            float4 b1 = *(const float4*)&Bs[kk][tx * 8 + 4];
            u64 ap[4] = { pack2(a0.x, a0.y), pack2(a0.z, a0.w),
                          pack2(a1.x, a1.y), pack2(a1.z, a1.w) };
            const float bb[8] = {b0.x, b0.y, b0.z, b0.w, b1.x, b1.y, b1.z, b1.w};
            #pragma unroll
            for (int j = 0; j < 8; ++j) {
                u64 bd = pack2(bb[j], bb[j]);
                #pragma unroll
                for (int ip = 0; ip < 4; ++ip) fma2(acc[ip][j], bd, ap[ip]);
            }
        }
    }

    // Epilogue: unpack row-pairs, write to per-head [h][row][64]
    const int colg = tx * 8;
    float* Oh = O + (size_t)(2 * hp + (colg >> 6)) * MROWS * DK;
    const int c = colg & 63;
    #pragma unroll
    for (int ip = 0; ip < 4; ++ip) {
        float2 u[8];
        #pragma unroll
        for (int j = 0; j < 8; ++j) u[j] = unpack2(acc[ip][j]);
        const int r0g = row0 + ty * 8 + 2 * ip;
        *(float4*)(Oh + (size_t)r0g * DK + c) =
            make_float4(u[0].x, u[1].x, u[2].x, u[3].x);
        *(float4*)(Oh + (size_t)r0g * DK + c + 4) =
            make_float4(u[4].x, u[5].x, u[6].x, u[7].x);
        *(float4*)(Oh + (size_t)(r0g + 1) * DK + c) =
            make_float4(u[0].y, u[1].y, u[2].y, u[3].y);
        *(float4*)(Oh + (size_t)(r0g + 1) * DK + c + 4) =
            make_float4(u[4].y, u[5].y, u[6].y, u[7].y);
    }
}

// ---------------------------------------------------------------------------
// Kernel 2: flash attention. 128 queries x 64-key tiles, 256 threads.
// QK: 8 rows x 4 keys per thread (row-pair f32x2), online softmax via smem
// m/l/scl arrays, PV: 8 rows x 4 d-cols per thread (col-pair f32x2).
// grid (16, 32), dynamic smem 103936 B -> 2 blocks/SM.
// ---------------------------------------------------------------------------
#define ATTN_SMEM ((64 * 132 + 64 * 68 + 64 * 64 + 128 * 68 + 3 * 128) * 4)

__global__ __launch_bounds__(256, 2) void attn_kernel()
{
    extern __shared__ float sm[];
    float* Qt     = sm;                   // [64 k][132]  (rows 0..127)
    float* Kt     = Qt + 64 * 132;        // [64 k][68]   (keys 0..63)
    float* Vs     = Kt + 64 * 68;         // [64 key][64 d]
    float* Ps     = Vs + 64 * 64;         // [128 row][68]
    float* sm_m   = Ps + 128 * 68;        // [128]
    float* sm_l   = sm_m + 128;
    float* sm_scl = sm_l + 128;

    const int hb = blockIdx.y;
    const int h  = hb >> 1, b = hb & 1;
    const int l0 = blockIdx.x * 128;
    const float* qh = g_qh + (size_t)hb * LL * DK;
    const float* kh = g_kh + (size_t)hb * LL * DK;
    const float* vh = g_vh + (size_t)hb * LL * DK;

    const int t  = threadIdx.x;
    const int tx = t & 15, ty = t >> 4;

    // Load Q tile transposed: Qt[k][row], 128 rows x 64 k
    #pragma unroll
    for (int i = 0; i < 8; ++i) {
        int f = i * 256 + t;
        int row = f >> 4, kc = (f & 15) * 4;
        float4 a = *(const float4*)(qh + (size_t)(l0 + row) * DK + kc);
        Qt[(kc + 0) * 132 + row] = a.x; Qt[(kc + 1) * 132 + row] = a.y;
        Qt[(kc + 2) * 132 + row] = a.z; Qt[(kc + 3) * 132 + row] = a.w;
    }
    if (t < 128) { sm_m[t] = -1e30f; sm_l[t] = 0.0f; }

    u64 acc[8][2] = {};   // [row i][col-pair]: rows ty*8+i, cols tx*4..tx*4+3
    __syncthreads();

    for (int j0 = 0; j0 < LL; j0 += 64) {
        // prefetch K,V
        float4 kr[4], vr[4];
        #pragma unroll
        for (int i = 0; i < 4; ++i) {
            int f = i * 256 + t;
            int key = f >> 4, kc = (f & 15) * 4;
            kr[i] = *(const float4*)(kh + (size_t)(j0 + key) * DK + kc);
            vr[i] = *(const float4*)(vh + (size_t)(j0 + key) * DK + kc);
        }
        if (j0) __syncthreads();   // prior PV done with Vs/Ps, QK with Kt
        #pragma unroll
        for (int i = 0; i < 4; ++i) {
            int f = i * 256 + t;
            int key = f >> 4, kc = (f & 15) * 4;
            Kt[(kc + 0) * 68 + key] = kr[i].x; Kt[(kc + 1) * 68 + key] = kr[i].y;
            Kt[(kc + 2) * 68 + key] = kr[i].z; Kt[(kc + 3) * 68 + key] = kr[i].w;
            *(float4*)&Vs[key * 64 + kc] = vr[i];
        }
        __syncthreads();

        // QK: s2[row-pair][key j]
        u64 s2[4][4] = {};
        #pragma unroll 8
        for (int kk = 0; kk < 64; ++kk) {
            float4 a0 = *(const float4*)&Qt[kk * 132 + ty * 8];
            float4 a1 = *(const float4*)&Qt[kk * 132 + ty * 8 + 4];
            float4 bv = *(const float4*)&Kt[kk * 68 + tx * 4];
            u64 ap[4] = { pack2(a0.x, a0.y), pack2(a0.z, a0.w),
                          pack2(a1.x, a1.y), pack2(a1.z, a1.w) };
            const float bb[4] = {bv.x, bv.y, bv.z, bv.w};
            #pragma unroll
            for (int j = 0; j < 4; ++j) {
                u64 bd = pack2(bb[j], bb[j]);
                #pragma unroll
                for (int ip = 0; ip < 4; ++ip) fma2(s2[ip][j], bd, ap[ip]);
            }
        }

        // softmax (online), rows handled across 16 tx lanes
        float sv[8][4];
        #pragma unroll
        for (int ip = 0; ip < 4; ++ip)
            #pragma unroll
            for (int j = 0; j < 4; ++j) {
                float2 v = unpack2(s2[ip][j]);
                sv[2 * ip][j] = v.x; sv[2 * ip + 1][j] = v.y;
            }
        #pragma unroll
        for (int i = 0; i < 8; ++i) {
            const int row = ty * 8 + i;
            float mx = fmaxf(fmaxf(sv[i][0], sv[i][1]), fmaxf(sv[i][2], sv[i][3]));
            #pragma unroll
            for (int off = 8; off; off >>= 1)
                mx = fmaxf(mx, __shfl_xor_sync(0xffffffffu, mx, off));
            const float mo = sm_m[row];
            const float mn = fmaxf(mo, mx);
            float4 p;
            p.x = __expf(sv[i][0] - mn); p.y = __expf(sv[i][1] - mn);
            p.z = __expf(sv[i][2] - mn); p.w = __expf(sv[i][3] - mn);
            float rs = (p.x + p.y) + (p.z + p.w);
            #pragma unroll
            for (int off = 8; off; off >>= 1)
                rs += __shfl_xor_sync(0xffffffffu, rs, off);
            if (tx == 0) {
                const float sc = __expf(mo - mn);
                sm_scl[row] = sc;
                sm_m[row]   = mn;
                sm_l[row]   = sm_l[row] * sc + rs;
            }
            *(float4*)&Ps[row * 68 + tx * 4] = p;
        }
        __syncthreads();

        // rescale + PV
        #pragma unroll
        for (int i = 0; i < 8; ++i) {
            const float sc = sm_scl[ty * 8 + i];
            const u64 sc2 = pack2(sc, sc);
            acc[i][0] = mul2(acc[i][0], sc2);
            acc[i][1] = mul2(acc[i][1], sc2);
        }
        for (int kk = 0; kk < 64; kk += 4) {
            float4 v0 = *(const float4*)&Vs[(kk + 0) * 64 + tx * 4];
            float4 v1 = *(const float4*)&Vs[(kk + 1) * 64 + tx * 4];
            float4 v2 = *(const float4*)&Vs[(kk + 2) * 64 + tx * 4];
            float4 v3 = *(const float4*)&Vs[(kk + 3) * 64 + tx * 4];
            u64 v0a = pack2(v0.x, v0.y), v0b = pack2(v0.z, v0.w);
            u64 v1a = pack2(v1.x, v1.y), v1b = pack2(v1.z, v1.w);
            u64 v2a = pack2(v2.x, v2.y), v2b = pack2(v2.z, v2.w);
            u64 v3a = pack2(v3.x, v3.y), v3b = pack2(v3.z, v3.w);
            #pragma unroll
            for (int i = 0; i < 8; ++i) {
                float4 pr = *(const float4*)&Ps[(ty * 8 + i) * 68 + kk];
                u64 px = pack2(pr.x, pr.x), py = pack2(pr.y, pr.y);
                u64 pz = pack2(pr.z, pr.z), pw = pack2(pr.w, pr.w);
                fma2(acc[i][0], px, v0a); fma2(acc[i][1], px, v0b);
                fma2(acc[i][0], py, v1a); fma2(acc[i][1], py, v1b);
                fma2(acc[i][0], pz, v2a); fma2(acc[i][1], pz, v2b);
                fma2(acc[i][0], pw, v3a); fma2(acc[i][1], pw, v3b);
            }
        }
    }

    // Epilogue: (acc / l) * qh -> concat layout
    #pragma unroll
    for (int i = 0; i < 8; ++i) {
        const int row = ty * 8 + i;
        const float invl = 1.0f / sm_l[row];
        float4 q4 = *(const float4*)(qh + (size_t)(l0 + row) * DK + tx * 4);
        float2 a0 = unpack2(acc[i][0]), a1 = unpack2(acc[i][1]);
        float4 o;
        o.x = a0.x * invl * q4.x; o.y = a0.y * invl * q4.y;
        o.z = a1.x * invl * q4.z; o.w = a1.y * invl * q4.w;
        *(float4*)(g_att + (size_t)(b * LL + l0 + row) * DM + h * DK + tx * 4) = o;
    }
}

// ---------------------------------------------------------------------------
// Kernel 3: Y = g_att @ w_proj^T + b. 128x128 tiles, NT, same micro-kernel.
// grid (32, 8), 256 threads.
// ---------------------------------------------------------------------------
__global__ __launch_bounds__(256, 2) void outproj_kernel(
    const float* __restrict__ wp, const float* __restrict__ bias,
    float* __restrict__ out)
{
    const int row0 = blockIdx.x * 128;
    const int col0 = blockIdx.y * 128;

    __shared__ float Ast[KT][132];
    __shared__ float Bst[KT][132];

    const int t  = threadIdx.x;
    const int tx = t & 15, ty = t >> 4;

    u64 acc[4][8] = {};

    for (int k0 = 0; k0 < DM; k0 += KT) {
        float4 ar[4], br[4];
        #pragma unroll
        for (int i = 0; i < 4; ++i) {
            int f = i * 256 + t;
            int row = f >> 3, kc = (f & 7) * 4;
            ar[i] = *(const float4*)(g_att + (size_t)(row0 + row) * DM + k0 + kc);
            br[i] = *(const float4*)(wp + (size_t)(col0 + row) * DM + k0 + kc);
        }
        __syncthreads();
        #pragma unroll
        for (int i = 0; i < 4; ++i) {
            int f = i * 256 + t;
            int row = f >> 3, kc = (f & 7) * 4;
            Ast[kc + 0][row] = ar[i].x; Ast[kc + 1][row] = ar[i].y;
            Ast[kc + 2][row] = ar[i].z; Ast[kc + 3][row] = ar[i].w;
            Bst[kc + 0][row] = br[i].x; Bst[kc + 1][row] = br[i].y;
            Bst[kc + 2][row] = br[i].z; Bst[kc + 3][row] = br[i].w;
        }
        __syncthreads();

        #pragma unroll 4
        for (int kk = 0; kk < KT; ++kk) {
            float4 a0 = *(const float4*)&Ast[kk][ty * 8];
            float4 a1 = *(const float4*)&Ast[kk][ty * 8 + 4];
            float4 b0 = *(const float4*)&Bst[kk][tx * 8];
            float4 b1 = *(const float4*)&Bst[kk][tx * 8 + 4];
            u64 ap[4] = { pack2(a0.x, a0.y), pack2(a0.z, a0.w),
                          pack2(a1.x, a1.y), pack2(a1.z, a1.w) };
            const float bb[8] = {b0.x, b0.y, b0.z, b0.w, b1.x, b1.y, b1.z, b1.w};
            #pragma unroll
            for (int j = 0; j < 8; ++j) {
                u64 bd = pack2(bb[j], bb[j]);
                #pragma unroll
                for (int ip = 0; ip < 4; ++ip) fma2(acc[ip][j], bd, ap[ip]);
            }
        }
    }

    float bv[8];
    #pragma unroll
    for (int j = 0; j < 8; ++j) bv[j] = bias[col0 + tx * 8 + j];

    #pragma unroll
    for (int ip = 0; ip < 4; ++ip) {
        float2 u[8];
        #pragma unroll
        for (int j = 0; j < 8; ++j) u[j] = unpack2(acc[ip][j]);
        const int rg = row0 + ty * 8 + 2 * ip;
        *(float4*)(out + (size_t)rg * DM + col0 + tx * 8) =
            make_float4(u[0].x + bv[0], u[1].x + bv[1], u[2].x + bv[2], u[3].x + bv[3]);
        *(float4*)(out + (size_t)rg * DM + col0 + tx * 8 + 4) =
            make_float4(u[4].x + bv[4], u[5].x + bv[5], u[6].x + bv[6], u[7].x + bv[7]);
        *(float4*)(out + (size_t)(rg + 1) * DM + col0 + tx * 8) =
            make_float4(u[0].y + bv[0], u[1].y + bv[1], u[2].y + bv[2], u[3].y + bv[3]);
        *(float4*)(out + (size_t)(rg + 1) * DM + col0 + tx * 8 + 4) =
            make_float4(u[4].y + bv[4], u[5].y + bv[5], u[6].y + bv[6], u[7].y + bv[7]);
    }
}

// ---------------------------------------------------------------------------
extern "C" void kernel_launch(void* const* d_in, const int* in_sizes, int n_in,
                              void* d_out, int out_size)
{
    const float* q  = (const float*)d_in[0];
    const float* k  = (const float*)d_in[1];
    const float* v  = (const float*)d_in[2];
    const float* wq = (const float*)d_in[3];
    const float* wk = (const float*)d_in[4];
    const float* wv = (const float*)d_in[5];
    const float* wp = (const float*)d_in[6];
    const float* bp = (const float*)d_in[7];
    float* out = (float*)d_out;

    cudaFuncSetAttribute(attn_kernel,
                         cudaFuncAttributeMaxDynamicSharedMemorySize, ATTN_SMEM);

    proj_kernel<<<dim3(MROWS / 128, NH / 2, 3), 256>>>(q, k, v, wq, wk, wv);
    attn_kernel<<<dim3(LL / 128, NH * BB), 256, ATTN_SMEM>>>();
    outproj_kernel<<<dim3(MROWS / 128, DM / 128), 256>>>(wp, bp, out);
}

// round 4
// speedup vs baseline: 2.5050x; 2.3572x over previous
#include <cuda_runtime.h>
#include <cuda_bf16.h>
#include <cstdint>

#define BB 2
#define LL 2048
#define DM 1024
#define NH 16
#define DK 64
#define MROWS (BB * LL)   // 4096

typedef __nv_bfloat16 bf16;
typedef __nv_bfloat162 bf162;

// ---------------------------------------------------------------------------
// Global scratch (no allocations allowed)
// ---------------------------------------------------------------------------
__device__ float g_qh[NH * MROWS * DK];         // fp32 per-head projections
__device__ float g_kh[NH * MROWS * DK];
__device__ float g_vh[NH * MROWS * DK];

__device__ bf16 g_xhi[3][MROWS * DM];           // split inputs q,k,v
__device__ bf16 g_xlo[3][MROWS * DM];
__device__ bf16 g_wthi[3 * NH * DK * DM];       // W transposed [z][h][n][k]
__device__ bf16 g_wtlo[3 * NH * DK * DM];
__device__ bf16 g_wphi[DM * DM];                // w_proj [n][k]
__device__ bf16 g_wplo[DM * DM];

__device__ bf16 g_qhi[NH * BB * LL * DK];       // [hb][l][k]
__device__ bf16 g_qlo[NH * BB * LL * DK];
__device__ bf16 g_khi[NH * BB * LL * DK];
__device__ bf16 g_klo[NH * BB * LL * DK];
__device__ bf16 g_vthi[NH * BB * DK * LL];      // [hb][d][l]  (V transposed)
__device__ bf16 g_vtlo[NH * BB * DK * LL];

__device__ bf16 g_atthi[MROWS * DM];            // attention output, split
__device__ bf16 g_attlo[MROWS * DM];

// ---------------------------------------------------------------------------
// PTX helpers (base-ISA only: mma.sync / ldmatrix / cp.async)
// ---------------------------------------------------------------------------
__device__ __forceinline__ uint32_t smem_u32(const void* p) {
    uint32_t a;
    asm("{ .reg .u64 t; cvta.to.shared.u64 t, %1; cvt.u32.u64 %0, t; }"
        : "=r"(a) : "l"(p));
    return a;
}
__device__ __forceinline__ void ldm4(uint32_t r[4], uint32_t a) {
    asm volatile("ldmatrix.sync.aligned.m8n8.x4.shared.b16 {%0,%1,%2,%3}, [%4];"
        : "=r"(r[0]), "=r"(r[1]), "=r"(r[2]), "=r"(r[3]) : "r"(a));
}
__device__ __forceinline__ void mma16816(float c[4], const uint32_t a[4],
                                         const uint32_t b[2]) {
    asm volatile("mma.sync.aligned.m16n8k16.row.col.f32.bf16.bf16.f32 "
        "{%0,%1,%2,%3}, {%4,%5,%6,%7}, {%8,%9}, {%0,%1,%2,%3};"
        : "+f"(c[0]), "+f"(c[1]), "+f"(c[2]), "+f"(c[3])
        : "r"(a[0]), "r"(a[1]), "r"(a[2]), "r"(a[3]), "r"(b[0]), "r"(b[1]));
}
#define CP16(dst, src) \
    asm volatile("cp.async.cg.shared.global [%0], [%1], 16;" \
                 :: "r"(dst), "l"(src) : "memory")
#define CP_COMMIT() asm volatile("cp.async.commit_group;" ::: "memory")
#define CP_WAIT1()  asm volatile("cp.async.wait_group 1;" ::: "memory")
#define CP_WAIT0()  asm volatile("cp.async.wait_group 0;" ::: "memory")

// 128B-row tile swizzle: unit = 16B column, XOR by row&7 (conflict-free ldmatrix)
__device__ __forceinline__ uint32_t swz(int row, int u) {
    return (uint32_t)(row * 128 + ((u ^ (row & 7)) << 4));
}
// pack two fp32 into bf16x2 (lo in low half)
__device__ __forceinline__ uint32_t pack_bf(float lo, float hi) {
    uint32_t r;
    asm("cvt.rn.bf16x2.f32 %0, %1, %2;" : "=r"(r) : "f"(hi), "f"(lo));
    return r;
}

// ---------------------------------------------------------------------------
// Conversion kernels
// ---------------------------------------------------------------------------
__global__ void conv_split_kernel(const float* __restrict__ src, int sel, int n4)
{
    bf16 *hi, *lo;
    if      (sel == 0) { hi = g_xhi[0]; lo = g_xlo[0]; }
    else if (sel == 1) { hi = g_xhi[1]; lo = g_xlo[1]; }
    else if (sel == 2) { hi = g_xhi[2]; lo = g_xlo[2]; }
    else               { hi = g_wphi;   lo = g_wplo;   }

    int i = blockIdx.x * 256 + threadIdx.x;
    if (i >= n4) return;
    float4 v = ((const float4*)src)[i];
    bf162 h01 = __floats2bfloat162_rn(v.x, v.y);
    bf162 h23 = __floats2bfloat162_rn(v.z, v.w);
    float2 f01 = __bfloat1622float2(h01);
    float2 f23 = __bfloat1622float2(h23);
    ((bf162*)hi)[2 * i]     = h01;
    ((bf162*)hi)[2 * i + 1] = h23;
    ((bf162*)lo)[2 * i]     = __floats2bfloat162_rn(v.x - f01.x, v.y - f01.y);
    ((bf162*)lo)[2 * i + 1] = __floats2bfloat162_rn(v.z - f23.x, v.w - f23.y);
}

__global__ void conv_wt_kernel(const float* __restrict__ wq,
                               const float* __restrict__ wk,
                               const float* __restrict__ wv)
{
    const int h = blockIdx.x, z = blockIdx.y;
    const float* W = (z == 0 ? wq : z == 1 ? wk : wv) + (size_t)h * DM * DK;
    bf16* hi = g_wthi + (size_t)(z * NH + h) * DK * DM;
    bf16* lo = g_wtlo + (size_t)(z * NH + h) * DK * DM;
    for (int idx = threadIdx.x; idx < DM * DK; idx += 256) {
        int k = idx >> 6, n = idx & 63;
        float x = W[idx];
        bf16 h0 = __float2bfloat16_rn(x);
        hi[(size_t)n * DM + k] = h0;
        lo[(size_t)n * DM + k] = __float2bfloat16_rn(x - __bfloat162float(h0));
    }
}

// g_qh / g_kh -> bf16 hi/lo split (elementwise)
__global__ void conv_qk_kernel()
{
    const int which = blockIdx.y;
    const float* src = which ? g_kh : g_qh;
    bf16* hi = which ? g_khi : g_qhi;
    bf16* lo = which ? g_klo : g_qlo;
    int i = blockIdx.x * 256 + threadIdx.x;
    const int n4 = NH * MROWS * DK / 4;
    if (i >= n4) return;
    float4 v = ((const float4*)src)[i];
    bf162 h01 = __floats2bfloat162_rn(v.x, v.y);
    bf162 h23 = __floats2bfloat162_rn(v.z, v.w);
    float2 f01 = __bfloat1622float2(h01);
    float2 f23 = __bfloat1622float2(h23);
    ((bf162*)hi)[2 * i]     = h01;
    ((bf162*)hi)[2 * i + 1] = h23;
    ((bf162*)lo)[2 * i]     = __floats2bfloat162_rn(v.x - f01.x, v.y - f01.y);
    ((bf162*)lo)[2 * i + 1] = __floats2bfloat162_rn(v.z - f23.x, v.w - f23.y);
}

// g_vh [hb][l][d] -> transposed split g_vt* [hb][d][l]
__global__ void conv_vt_kernel()
{
    __shared__ float ts[64][65];
    const int hb = blockIdx.y;
    const int l0 = blockIdx.x * 64;
    const float* src = g_vh + (size_t)hb * LL * DK;
    const int t = threadIdx.x;
    for (int i = 0; i < 16; ++i) {
        int idx = i * 256 + t;
        int r = idx >> 6, d = idx & 63;
        ts[r][d] = src[(size_t)(l0 + r) * DK + d];
    }
    __syncthreads();
    for (int i = 0; i < 16; ++i) {
        int idx = i * 256 + t;
        int d = idx >> 6, c = idx & 63;
        float x = ts[c][d];
        bf16 h0 = __float2bfloat16_rn(x);
        size_t o = ((size_t)hb * DK + d) * LL + l0 + c;
        g_vthi[o] = h0;
        g_vtlo[o] = __float2bfloat16_rn(x - __bfloat162float(h0));
    }
}

// ---------------------------------------------------------------------------
// GEMM core: C[128x128] (fp32 frags) = A[128,1024] @ B[128,1024]^T
// 2-term bf16 split (3 mma per product), cp.async double-buffered 64-K chunks.
// 8 warps: warp w -> m offset (w&1)*64, n offset (w>>1)*32.
// ---------------------------------------------------------------------------
#define GEMM_SMEM (2 * 65536 + 128)

__device__ __forceinline__ void gemm_fill(uint32_t base,
    const bf16* __restrict__ Ahi, const bf16* __restrict__ Alo, size_t ar0,
    const bf16* __restrict__ Bhi, const bf16* __restrict__ Blo, size_t br0,
    int k0)
{
    const int t = threadIdx.x;
    #pragma unroll
    for (int i = 0; i < 4; ++i) {
        int g = i * 256 + t;
        int row = g >> 3, u = g & 7;
        size_t goff = (size_t)row * DM + k0 + u * 8;
        uint32_t s = swz(row, u);
        CP16(base + s,         Ahi + (size_t)ar0 * DM + goff);
        CP16(base + 16384 + s, Alo + (size_t)ar0 * DM + goff);
        CP16(base + 32768 + s, Bhi + (size_t)br0 * DM + goff);
        CP16(base + 49152 + s, Blo + (size_t)br0 * DM + goff);
    }
}

__device__ __forceinline__ void gemm_core(uint32_t sb,
    const bf16* Ahi, const bf16* Alo, size_t ar0,
    const bf16* Bhi, const bf16* Blo, size_t br0,
    float C[4][4][4])
{
    const int t = threadIdx.x, w = t >> 5, l = t & 31;
    const int wm = (w & 1) * 64, wn = (w >> 1) * 32;
    const int mi = l >> 3;

    gemm_fill(sb, Ahi, Alo, ar0, Bhi, Blo, br0, 0);
    CP_COMMIT();

    for (int c = 0; c < 16; ++c) {
        if (c + 1 < 16) {
            gemm_fill(sb + ((c + 1) & 1) * 65536, Ahi, Alo, ar0, Bhi, Blo, br0,
                      (c + 1) * 64);
            CP_COMMIT();
            CP_WAIT1();
        } else {
            CP_WAIT0();
        }
        __syncthreads();
        const uint32_t tb = sb + (c & 1) * 65536;

        #pragma unroll
        for (int kt = 0; kt < 4; ++kt) {
            uint32_t ahi[4][4], alo[4][4];
            #pragma unroll
            for (int i = 0; i < 4; ++i) {
                int row = wm + 16 * i + (l & 7) + ((mi & 1) << 3);
                int u = kt * 2 + (mi >> 1);
                ldm4(ahi[i], tb + swz(row, u));
                ldm4(alo[i], tb + 16384 + swz(row, u));
            }
            uint32_t bhi[4][2], blo[4][2];
            #pragma unroll
            for (int jp = 0; jp < 2; ++jp) {
                int row = wn + jp * 16 + ((mi >> 1) << 3) + (l & 7);
                int u = kt * 2 + (mi & 1);
                uint32_t r4[4];
                ldm4(r4, tb + 32768 + swz(row, u));
                bhi[2*jp][0] = r4[0]; bhi[2*jp][1] = r4[1];
                bhi[2*jp+1][0] = r4[2]; bhi[2*jp+1][1] = r4[3];
                ldm4(r4, tb + 49152 + swz(row, u));
                blo[2*jp][0] = r4[0]; blo[2*jp][1] = r4[1];
                blo[2*jp+1][0] = r4[2]; blo[2*jp+1][1] = r4[3];
            }
            #pragma unroll
            for (int i = 0; i < 4; ++i)
                #pragma unroll
                for (int j = 0; j < 4; ++j) {
                    mma16816(C[i][j], ahi[i], bhi[j]);
                    mma16816(C[i][j], ahi[i], blo[j]);
                    mma16816(C[i][j], alo[i], bhi[j]);
                }
        }
        __syncthreads();
    }
}

// ---------------------------------------------------------------------------
// Kernel: per-head-pair input projections. grid (32, 8, 3)
// ---------------------------------------------------------------------------
__global__ __launch_bounds__(256, 1) void gemm_proj_mma()
{
    extern __shared__ char smraw[];
    uint32_t sb = (smem_u32(smraw) + 127) & ~127u;
    const int z = blockIdx.z, hp = blockIdx.y;
    const size_t row0 = (size_t)blockIdx.x * 128;

    float C[4][4][4] = {};
    gemm_core(sb, g_xhi[z], g_xlo[z], row0,
              g_wthi + (size_t)(z * NH + 2 * hp) * DK * DM,
              g_wtlo + (size_t)(z * NH + 2 * hp) * DK * DM, 0, C);

    const int t = threadIdx.x, w = t >> 5, l = t & 31;
    const int gid = l >> 2, tig = l & 3;
    const int wm = (w & 1) * 64, wn = (w >> 1) * 32;
    float* dst = (z == 0 ? g_qh : z == 1 ? g_kh : g_vh);

    #pragma unroll
    for (int i = 0; i < 4; ++i)
        #pragma unroll
        for (int j = 0; j < 4; ++j) {
            int col = wn + 8 * j + 2 * tig;
            int head = 2 * hp + (col >> 6), d = col & 63;
            size_t r = row0 + wm + 16 * i + gid;
            float* O = dst + (size_t)head * MROWS * DK;
            *(float2*)(O + r * DK + d) = make_float2(C[i][j][0], C[i][j][1]);
            *(float2*)(O + (r + 8) * DK + d) = make_float2(C[i][j][2], C[i][j][3]);
        }
}

// ---------------------------------------------------------------------------
// Kernel: output projection + bias. grid (32, 8)
// ---------------------------------------------------------------------------
__global__ __launch_bounds__(256, 1) void gemm_out_mma(
    const float* __restrict__ bias, float* __restrict__ out)
{
    extern __shared__ char smraw[];
    uint32_t sb = (smem_u32(smraw) + 127) & ~127u;
    const size_t row0 = (size_t)blockIdx.x * 128;
    const size_t col0 = (size_t)blockIdx.y * 128;

    float C[4][4][4] = {};
    gemm_core(sb, g_atthi, g_attlo, row0, g_wphi, g_wplo, col0, C);

    const int t = threadIdx.x, w = t >> 5, l = t & 31;
    const int gid = l >> 2, tig = l & 3;
    const int wm = (w & 1) * 64, wn = (w >> 1) * 32;

    #pragma unroll
    for (int i = 0; i < 4; ++i)
        #pragma unroll
        for (int j = 0; j < 4; ++j) {
            size_t col = col0 + wn + 8 * j + 2 * tig;
            size_t r = row0 + wm + 16 * i + gid;
            float2 b2 = *(const float2*)(bias + col);
            *(float2*)(out + r * DM + col) =
                make_float2(C[i][j][0] + b2.x, C[i][j][1] + b2.y);
            *(float2*)(out + (r + 8) * DM + col) =
                make_float2(C[i][j][2] + b2.x, C[i][j][3] + b2.y);
        }
}

// ---------------------------------------------------------------------------
// Flash attention on HMMA. grid (16, 32): 128 q-rows per CTA, 64-key tiles.
// Warp w owns q rows [w*16, w*16+16). Split precision: 3 mma per product.
// ---------------------------------------------------------------------------
#define ATTN_SMEM (32768 + 2 * 32768 + 128)

__device__ __forceinline__ void attn_fill(uint32_t base,
    const bf16* khi, const bf16* klo, const bf16* vthi, const bf16* vtlo,
    int j0)
{
    const int t = threadIdx.x;
    #pragma unroll
    for (int i = 0; i < 2; ++i) {
        int g = i * 256 + t;
        int row = g >> 3, u = g & 7;
        uint32_t s = swz(row, u);
        CP16(base + s,         khi  + (size_t)(j0 + row) * DK + u * 8);
        CP16(base + 8192 + s,  klo  + (size_t)(j0 + row) * DK + u * 8);
        CP16(base + 16384 + s, vthi + (size_t)row * LL + j0 + u * 8);
        CP16(base + 24576 + s, vtlo + (size_t)row * LL + j0 + u * 8);
    }
}

__global__ __launch_bounds__(256, 1) void attn_mma()
{
    extern __shared__ char smraw[];
    const uint32_t sb = (smem_u32(smraw) + 127) & ~127u;
    const uint32_t QHI = sb, QLO = sb + 16384, ST0 = sb + 32768;

    const int hb = blockIdx.y;
    const int h = hb >> 1, b = hb & 1;
    const int l0 = blockIdx.x * 128;
    const bf16* qhi = g_qhi + (size_t)hb * LL * DK;
    const bf16* qlo = g_qlo + (size_t)hb * LL * DK;
    const bf16* khi = g_khi + (size_t)hb * LL * DK;
    const bf16* klo = g_klo + (size_t)hb * LL * DK;
    const bf16* vthi = g_vthi + (size_t)hb * DK * LL;
    const bf16* vtlo = g_vtlo + (size_t)hb * DK * LL;

    const int t = threadIdx.x, w = t >> 5, l = t & 31;
    const int gid = l >> 2, tig = l & 3;
    const int mi = l >> 3;

    // Load Q tile (hi+lo) into smem
    #pragma unroll
    for (int i = 0; i < 4; ++i) {
        int g = i * 256 + t;
        int row = g >> 3, u = g & 7;
        uint32_t s = swz(row, u);
        *(uint4*)(smraw + (QHI - sb) + s) =
            *(const uint4*)(qhi + (size_t)(l0 + row) * DK + u * 8);
        *(uint4*)(smraw + (QLO - sb) + s) =
            *(const uint4*)(qlo + (size_t)(l0 + row) * DK + u * 8);
    }
    attn_fill(ST0, khi, klo, vthi, vtlo, 0);
    CP_COMMIT();
    __syncthreads();

    // Q fragments (resident): 4 k-tiles x (hi,lo)
    uint32_t qfh[4][4], qfl[4][4];
    #pragma unroll
    for (int kt = 0; kt < 4; ++kt) {
        int row = w * 16 + (l & 7) + ((mi & 1) << 3);
        int u = kt * 2 + (mi >> 1);
        ldm4(qfh[kt], QHI + swz(row, u));
        ldm4(qfl[kt], QLO + swz(row, u));
    }

    float o[8][4] = {};
    float m0 = -1e30f, m1 = -1e30f, l0s = 0.f, l1s = 0.f;

    for (int jt = 0; jt < 32; ++jt) {
        if (jt + 1 < 32) {
            attn_fill(ST0 + ((jt + 1) & 1) * 32768, khi, klo, vthi, vtlo,
                      (jt + 1) * 64);
            CP_COMMIT();
            CP_WAIT1();
        } else {
            CP_WAIT0();
        }
        __syncthreads();
        const uint32_t tb = ST0 + (jt & 1) * 32768;

        // ---- S = Q K^T (split) ----
        float s[8][4] = {};
        #pragma unroll
        for (int kt = 0; kt < 4; ++kt) {
            uint32_t kh[8][2], kl[8][2];
            #pragma unroll
            for (int jp = 0; jp < 4; ++jp) {
                int row = jp * 16 + ((mi >> 1) << 3) + (l & 7);
                int u = kt * 2 + (mi & 1);
                uint32_t r4[4];
                ldm4(r4, tb + swz(row, u));
                kh[2*jp][0] = r4[0]; kh[2*jp][1] = r4[1];
                kh[2*jp+1][0] = r4[2]; kh[2*jp+1][1] = r4[3];
                ldm4(r4, tb + 8192 + swz(row, u));
                kl[2*jp][0] = r4[0]; kl[2*jp][1] = r4[1];
                kl[2*jp+1][0] = r4[2]; kl[2*jp+1][1] = r4[3];
            }
            #pragma unroll
            for (int n = 0; n < 8; ++n) {
                mma16816(s[n], qfh[kt], kh[n]);
                mma16816(s[n], qfh[kt], kl[n]);
                mma16816(s[n], qfl[kt], kh[n]);
            }
        }

        // ---- online softmax ----
        float rm0 = -1e30f, rm1 = -1e30f;
        #pragma unroll
        for (int n = 0; n < 8; ++n) {
            rm0 = fmaxf(rm0, fmaxf(s[n][0], s[n][1]));
            rm1 = fmaxf(rm1, fmaxf(s[n][2], s[n][3]));
        }
        rm0 = fmaxf(rm0, __shfl_xor_sync(0xffffffffu, rm0, 1));
        rm0 = fmaxf(rm0, __shfl_xor_sync(0xffffffffu, rm0, 2));
        rm1 = fmaxf(rm1, __shfl_xor_sync(0xffffffffu, rm1, 1));
        rm1 = fmaxf(rm1, __shfl_xor_sync(0xffffffffu, rm1, 2));
        const float mn0 = fmaxf(m0, rm0), mn1 = fmaxf(m1, rm1);
        const float sc0 = __expf(m0 - mn0), sc1 = __expf(m1 - mn1);
        m0 = mn0; m1 = mn1;
        float rs0 = 0.f, rs1 = 0.f;
        #pragma unroll
        for (int n = 0; n < 8; ++n) {
            s[n][0] = __expf(s[n][0] - mn0); s[n][1] = __expf(s[n][1] - mn0);
            s[n][2] = __expf(s[n][2] - mn1); s[n][3] = __expf(s[n][3] - mn1);
            rs0 += s[n][0] + s[n][1];
            rs1 += s[n][2] + s[n][3];
        }
        rs0 += __shfl_xor_sync(0xffffffffu, rs0, 1);
        rs0 += __shfl_xor_sync(0xffffffffu, rs0, 2);
        rs1 += __shfl_xor_sync(0xffffffffu, rs1, 1);
        rs1 += __shfl_xor_sync(0xffffffffu, rs1, 2);
        l0s = l0s * sc0 + rs0;
        l1s = l1s * sc1 + rs1;
        #pragma unroll
        for (int n = 0; n < 8; ++n) {
            o[n][0] *= sc0; o[n][1] *= sc0;
            o[n][2] *= sc1; o[n][3] *= sc1;
        }

        // ---- P -> A fragments (split) + PV ----
        #pragma unroll
        for (int kt = 0; kt < 4; ++kt) {
            float pv[8] = { s[2*kt][0], s[2*kt][1], s[2*kt][2], s[2*kt][3],
                            s[2*kt+1][0], s[2*kt+1][1], s[2*kt+1][2], s[2*kt+1][3] };
            float ph[8], plr[8];
            #pragma unroll
            for (int e = 0; e < 8; ++e) {
                bf16 hbv = __float2bfloat16_rn(pv[e]);
                ph[e] = __bfloat162float(hbv);
                plr[e] = pv[e] - ph[e];
            }
            uint32_t pah[4] = { pack_bf(ph[0], ph[1]), pack_bf(ph[2], ph[3]),
                                pack_bf(ph[4], ph[5]), pack_bf(ph[6], ph[7]) };
            uint32_t pal[4] = { pack_bf(plr[0], plr[1]), pack_bf(plr[2], plr[3]),
                                pack_bf(plr[4], plr[5]), pack_bf(plr[6], plr[7]) };
            uint32_t vh[8][2], vl[8][2];
            #pragma unroll
            for (int jp = 0; jp < 4; ++jp) {
                int row = jp * 16 + ((mi >> 1) << 3) + (l & 7);
                int u = kt * 2 + (mi & 1);
                uint32_t r4[4];
                ldm4(r4, tb + 16384 + swz(row, u));
                vh[2*jp][0] = r4[0]; vh[2*jp][1] = r4[1];
                vh[2*jp+1][0] = r4[2]; vh[2*jp+1][1] = r4[3];
                ldm4(r4, tb + 24576 + swz(row, u));
                vl[2*jp][0] = r4[0]; vl[2*jp][1] = r4[1];
                vl[2*jp+1][0] = r4[2]; vl[2*jp+1][1] = r4[3];
            }
            #pragma unroll
            for (int n = 0; n < 8; ++n) {
                mma16816(o[n], pah, vh[n]);
                mma16816(o[n], pah, vl[n]);
                mma16816(o[n], pal, vh[n]);
            }
        }
        __syncthreads();
    }

    // ---- epilogue: (o / l) * q, split to bf16 hi/lo ----
    const float inv0 = 1.0f / l0s, inv1 = 1.0f / l1s;
    const size_t r0 = l0 + w * 16 + gid, r1 = r0 + 8;
    #pragma unroll
    for (int n = 0; n < 8; ++n) {
        const int d = 8 * n + 2 * tig;
        bf162 qh2a = *(const bf162*)(qhi + ((size_t)r0) * DK + d);
        bf162 ql2a = *(const bf162*)(qlo + ((size_t)r0) * DK + d);
        bf162 qh2b = *(const bf162*)(qhi + ((size_t)r1) * DK + d);
        bf162 ql2b = *(const bf162*)(qlo + ((size_t)r1) * DK + d);
        float qa0 = __bfloat162float(qh2a.x) + __bfloat162float(ql2a.x);
        float qa1 = __bfloat162float(qh2a.y) + __bfloat162float(ql2a.y);
        float qb0 = __bfloat162float(qh2b.x) + __bfloat162float(ql2b.x);
        float qb1 = __bfloat162float(qh2b.y) + __bfloat162float(ql2b.y);
        float v00 = o[n][0] * inv0 * qa0, v01 = o[n][1] * inv0 * qa1;
        float v10 = o[n][2] * inv1 * qb0, v11 = o[n][3] * inv1 * qb1;

        size_t o0 = ((size_t)b * LL + r0) * DM + h * DK + d;
        size_t o1 = ((size_t)b * LL + r1) * DM + h * DK + d;
        bf162 h00 = __floats2bfloat162_rn(v00, v01);
        bf162 h10 = __floats2bfloat162_rn(v10, v11);
        float2 f00 = __bfloat1622float2(h00);
        float2 f10 = __bfloat1622float2(h10);
        *(bf162*)(g_atthi + o0) = h00;
        *(bf162*)(g_atthi + o1) = h10;
        *(bf162*)(g_attlo + o0) = __floats2bfloat162_rn(v00 - f00.x, v01 - f00.y);
        *(bf162*)(g_attlo + o1) = __floats2bfloat162_rn(v10 - f10.x, v11 - f10.y);
    }
}

// ---------------------------------------------------------------------------
extern "C" void kernel_launch(void* const* d_in, const int* in_sizes, int n_in,
                              void* d_out, int out_size)
{
    const float* q  = (const float*)d_in[0];
    const float* k  = (const float*)d_in[1];
    const float* v  = (const float*)d_in[2];
    const float* wq = (const float*)d_in[3];
    const float* wk = (const float*)d_in[4];
    const float* wv = (const float*)d_in[5];
    const float* wp = (const float*)d_in[6];
    const float* bp = (const float*)d_in[7];
    float* out = (float*)d_out;

    cudaFuncSetAttribute(gemm_proj_mma,
                         cudaFuncAttributeMaxDynamicSharedMemorySize, GEMM_SMEM);
    cudaFuncSetAttribute(gemm_out_mma,
                         cudaFuncAttributeMaxDynamicSharedMemorySize, GEMM_SMEM);
    cudaFuncSetAttribute(attn_mma,
                         cudaFuncAttributeMaxDynamicSharedMemorySize, ATTN_SMEM);

    const int n4x = MROWS * DM / 4;
    const int n4w = DM * DM / 4;
    conv_split_kernel<<<(n4x + 255) / 256, 256>>>(q,  0, n4x);
    conv_split_kernel<<<(n4x + 255) / 256, 256>>>(k,  1, n4x);
    conv_split_kernel<<<(n4x + 255) / 256, 256>>>(v,  2, n4x);
    conv_split_kernel<<<(n4w + 255) / 256, 256>>>(wp, 3, n4w);
    conv_wt_kernel<<<dim3(NH, 3), 256>>>(wq, wk, wv);

    gemm_proj_mma<<<dim3(MROWS / 128, NH / 2, 3), 256, GEMM_SMEM>>>();

    const int n4qk = NH * MROWS * DK / 4;
    conv_qk_kernel<<<dim3((n4qk + 255) / 256, 2), 256>>>();
    conv_vt_kernel<<<dim3(LL / 64, NH * BB), 256>>>();

    attn_mma<<<dim3(LL / 128, NH * BB), 256, ATTN_SMEM>>>();

    gemm_out_mma<<<dim3(MROWS / 128, DM / 128), 256, GEMM_SMEM>>>(bp, out);
}

// round 5
// speedup vs baseline: 3.4495x; 1.3771x over previous
#include <cuda_runtime.h>
#include <cuda_fp16.h>
#include <cstdint>

#define BB 2
#define LL 2048
#define DM 1024
#define NH 16
#define DK 64
#define MROWS (BB * LL)   // 4096

typedef __half hf;

// ---------------------------------------------------------------------------
// Global scratch (no allocations allowed)
// ---------------------------------------------------------------------------
__device__ float g_vh[NH * MROWS * DK];         // fp32 V projections (pre-transpose)

__device__ hf g_xhi[3][MROWS * DM];             // split inputs q,k,v (v: hi only)
__device__ hf g_xlo[3][MROWS * DM];
__device__ hf g_wthi[3 * NH * DK * DM];         // W transposed [z][h][n][k]
__device__ hf g_wtlo[3 * NH * DK * DM];
__device__ hf g_wphi[DM * DM];                  // w_proj [n][k]
__device__ hf g_wplo[DM * DM];

__device__ hf g_qhi[NH * BB * LL * DK];         // [hb][l][k]
__device__ hf g_qlo[NH * BB * LL * DK];
__device__ hf g_khi[NH * BB * LL * DK];
__device__ hf g_klo[NH * BB * LL * DK];
__device__ hf g_vthi[NH * BB * DK * LL];        // [hb][d][l]  (V transposed)
__device__ hf g_vtlo[NH * BB * DK * LL];

__device__ hf g_atthi[MROWS * DM];              // attention output (hi only)

// ---------------------------------------------------------------------------
// PTX helpers (base-ISA: mma.sync / ldmatrix / cp.async)
// ---------------------------------------------------------------------------
__device__ __forceinline__ uint32_t smem_u32(const void* p) {
    uint32_t a;
    asm("{ .reg .u64 t; cvta.to.shared.u64 t, %1; cvt.u32.u64 %0, t; }"
        : "=r"(a) : "l"(p));
    return a;
}
__device__ __forceinline__ void ldm4(uint32_t r[4], uint32_t a) {
    asm volatile("ldmatrix.sync.aligned.m8n8.x4.shared.b16 {%0,%1,%2,%3}, [%4];"
        : "=r"(r[0]), "=r"(r[1]), "=r"(r[2]), "=r"(r[3]) : "r"(a));
}
__device__ __forceinline__ void mma16816(float c[4], const uint32_t a[4],
                                         const uint32_t b[2]) {
    asm volatile("mma.sync.aligned.m16n8k16.row.col.f32.f16.f16.f32 "
        "{%0,%1,%2,%3}, {%4,%5,%6,%7}, {%8,%9}, {%0,%1,%2,%3};"
        : "+f"(c[0]), "+f"(c[1]), "+f"(c[2]), "+f"(c[3])
        : "r"(a[0]), "r"(a[1]), "r"(a[2]), "r"(a[3]), "r"(b[0]), "r"(b[1]));
}
#define CP16(dst, src) \
    asm volatile("cp.async.cg.shared.global [%0], [%1], 16;" \
                 :: "r"(dst), "l"(src) : "memory")
#define CP_COMMIT() asm volatile("cp.async.commit_group;" ::: "memory")
#define CP_WAIT1()  asm volatile("cp.async.wait_group 1;" ::: "memory")
#define CP_WAIT0()  asm volatile("cp.async.wait_group 0;" ::: "memory")

// 128B-row tile swizzle: unit = 16B column, XOR by row&7 (conflict-free ldmatrix)
__device__ __forceinline__ uint32_t swz(int row, int u) {
    return (uint32_t)(row * 128 + ((u ^ (row & 7)) << 4));
}
// pack two fp32 into f16x2 (first arg -> low half)
__device__ __forceinline__ uint32_t pack_hf(float lo, float hi) {
    uint32_t r;
    asm("cvt.rn.f16x2.f32 %0, %1, %2;" : "=r"(r) : "f"(hi), "f"(lo));
    return r;
}

// ---------------------------------------------------------------------------
// Conversion kernels
// ---------------------------------------------------------------------------
__global__ void conv_split_kernel(const float* __restrict__ src, int sel, int n4)
{
    hf *hi, *lo;
    bool wlo = true;
    if      (sel == 0) { hi = g_xhi[0]; lo = g_xlo[0]; }
    else if (sel == 1) { hi = g_xhi[1]; lo = g_xlo[1]; }
    else if (sel == 2) { hi = g_xhi[2]; lo = nullptr; wlo = false; }
    else               { hi = g_wphi;   lo = g_wplo;   }

    int i = blockIdx.x * 256 + threadIdx.x;
    if (i >= n4) return;
    float4 v = ((const float4*)src)[i];
    uint32_t h01 = pack_hf(v.x, v.y);
    uint32_t h23 = pack_hf(v.z, v.w);
    ((uint32_t*)hi)[2 * i]     = h01;
    ((uint32_t*)hi)[2 * i + 1] = h23;
    if (wlo) {
        __half2 f01 = *(__half2*)&h01, f23 = *(__half2*)&h23;
        ((uint32_t*)lo)[2 * i] =
            pack_hf(v.x - __half2float(f01.x), v.y - __half2float(f01.y));
        ((uint32_t*)lo)[2 * i + 1] =
            pack_hf(v.z - __half2float(f23.x), v.w - __half2float(f23.y));
    }
}

// Transpose + split weights: Wt[z][h][n][k] = W_z[h][k][n], via smem transpose
__global__ void conv_wt_kernel(const float* __restrict__ wq,
                               const float* __restrict__ wk,
                               const float* __restrict__ wv)
{
    __shared__ float ts[64][65];
    const int h = blockIdx.x, z = blockIdx.y;
    const float* W = (z == 0 ? wq : z == 1 ? wk : wv) + (size_t)h * DM * DK;
    hf* hi = g_wthi + (size_t)(z * NH + h) * DK * DM;
    hf* lo = g_wtlo + (size_t)(z * NH + h) * DK * DM;
    const int t = threadIdx.x;
    for (int k0 = 0; k0 < DM; k0 += 64) {
        __syncthreads();
        for (int i = 0; i < 16; ++i) {
            int idx = i * 256 + t;
            int r = idx >> 6, c = idx & 63;
            ts[r][c] = W[(size_t)(k0 + r) * DK + c];   // [k][n] coalesced
        }
        __syncthreads();
        for (int i = 0; i < 16; ++i) {
            int idx = i * 256 + t;
            int n = idx >> 6, c = idx & 63;            // write [n][k] coalesced
            float x = ts[c][n];
            hf h0 = __float2half_rn(x);
            hi[(size_t)n * DM + k0 + c] = h0;
            lo[(size_t)n * DM + k0 + c] = __float2half_rn(x - __half2float(h0));
        }
    }
}

// g_vh [hb][l][d] -> transposed split g_vt* [hb][d][l]
__global__ void conv_vt_kernel()
{
    __shared__ float ts[64][65];
    const int hb = blockIdx.y;
    const int l0 = blockIdx.x * 64;
    const float* src = g_vh + (size_t)hb * LL * DK;
    const int t = threadIdx.x;
    for (int i = 0; i < 16; ++i) {
        int idx = i * 256 + t;
        int r = idx >> 6, d = idx & 63;
        ts[r][d] = src[(size_t)(l0 + r) * DK + d];
    }
    __syncthreads();
    for (int i = 0; i < 16; ++i) {
        int idx = i * 256 + t;
        int d = idx >> 6, c = idx & 63;
        float x = ts[c][d];
        hf h0 = __float2half_rn(x);
        size_t o = ((size_t)hb * DK + d) * LL + l0 + c;
        g_vthi[o] = h0;
        g_vtlo[o] = __float2half_rn(x - __half2float(h0));
    }
}

// ---------------------------------------------------------------------------
// GEMM core: C[128x128] (fp32 frags) = A[128,1024] @ B[128,1024]^T
// USE_ALO: 3-MMA split (ah*bh + ah*bl + al*bh); else 2-MMA (ah*bh + ah*bl).
// cp.async double-buffered 64-K chunks. 8 warps: m offset (w&1)*64, n (w>>1)*32.
// ---------------------------------------------------------------------------
#define GEMM_SMEM (2 * 65536 + 128)

template <bool USE_ALO>
__device__ __forceinline__ void gemm_fill(uint32_t base,
    const hf* __restrict__ Ahi, const hf* __restrict__ Alo, size_t ar0,
    const hf* __restrict__ Bhi, const hf* __restrict__ Blo, size_t br0,
    int k0)
{
    const int t = threadIdx.x;
    #pragma unroll
    for (int i = 0; i < 4; ++i) {
        int g = i * 256 + t;
        int row = g >> 3, u = g & 7;
        size_t goff = (size_t)row * DM + k0 + u * 8;
        uint32_t s = swz(row, u);
        CP16(base + s, Ahi + (size_t)ar0 * DM + goff);
        if (USE_ALO) CP16(base + 16384 + s, Alo + (size_t)ar0 * DM + goff);
        CP16(base + 32768 + s, Bhi + (size_t)br0 * DM + goff);
        CP16(base + 49152 + s, Blo + (size_t)br0 * DM + goff);
    }
}

template <bool USE_ALO>
__device__ __forceinline__ void gemm_core(uint32_t sb,
    const hf* Ahi, const hf* Alo, size_t ar0,
    const hf* Bhi, const hf* Blo, size_t br0,
    float C[4][4][4])
{
    const int t = threadIdx.x, w = t >> 5, l = t & 31;
    const int wm = (w & 1) * 64, wn = (w >> 1) * 32;
    const int mi = l >> 3;

    gemm_fill<USE_ALO>(sb, Ahi, Alo, ar0, Bhi, Blo, br0, 0);
    CP_COMMIT();

    for (int c = 0; c < 16; ++c) {
        if (c + 1 < 16) {
            gemm_fill<USE_ALO>(sb + ((c + 1) & 1) * 65536, Ahi, Alo, ar0,
                               Bhi, Blo, br0, (c + 1) * 64);
            CP_COMMIT();
            CP_WAIT1();
        } else {
            CP_WAIT0();
        }
        __syncthreads();
        const uint32_t tb = sb + (c & 1) * 65536;

        #pragma unroll
        for (int kt = 0; kt < 4; ++kt) {
            uint32_t ahi[4][4], alo[4][4];
            #pragma unroll
            for (int i = 0; i < 4; ++i) {
                int row = wm + 16 * i + (l & 7) + ((mi & 1) << 3);
                int u = kt * 2 + (mi >> 1);
                ldm4(ahi[i], tb + swz(row, u));
                if (USE_ALO) ldm4(alo[i], tb + 16384 + swz(row, u));
            }
            uint32_t bhi[4][2], blo[4][2];
            #pragma unroll
            for (int jp = 0; jp < 2; ++jp) {
                int row = wn + jp * 16 + ((mi >> 1) << 3) + (l & 7);
                int u = kt * 2 + (mi & 1);
                uint32_t r4[4];
                ldm4(r4, tb + 32768 + swz(row, u));
                bhi[2*jp][0] = r4[0]; bhi[2*jp][1] = r4[1];
                bhi[2*jp+1][0] = r4[2]; bhi[2*jp+1][1] = r4[3];
                ldm4(r4, tb + 49152 + swz(row, u));
                blo[2*jp][0] = r4[0]; blo[2*jp][1] = r4[1];
                blo[2*jp+1][0] = r4[2]; blo[2*jp+1][1] = r4[3];
            }
            #pragma unroll
            for (int i = 0; i < 4; ++i)
                #pragma unroll
                for (int j = 0; j < 4; ++j) {
                    mma16816(C[i][j], ahi[i], bhi[j]);
                    mma16816(C[i][j], ahi[i], blo[j]);
                    if (USE_ALO) mma16816(C[i][j], alo[i], bhi[j]);
                }
        }
        __syncthreads();
    }
}

// ---------------------------------------------------------------------------
// Kernel: per-head-pair input projections. grid (32, 8, 3)
// z=0 (q), z=1 (k): 3-MMA, epilogue writes fp16 hi/lo split to g_q*/g_k*.
// z=2 (v): 2-MMA, epilogue writes fp32 g_vh (transposed+split later).
// ---------------------------------------------------------------------------
__global__ __launch_bounds__(256, 1) void gemm_proj_mma()
{
    extern __shared__ char smraw[];
    uint32_t sb = (smem_u32(smraw) + 127) & ~127u;
    const int z = blockIdx.z, hp = blockIdx.y;
    const size_t row0 = (size_t)blockIdx.x * 128;

    float C[4][4][4] = {};
    const hf* Bhi = g_wthi + (size_t)(z * NH + 2 * hp) * DK * DM;
    const hf* Blo = g_wtlo + (size_t)(z * NH + 2 * hp) * DK * DM;
    if (z < 2)
        gemm_core<true >(sb, g_xhi[z], g_xlo[z], row0, Bhi, Blo, 0, C);
    else
        gemm_core<false>(sb, g_xhi[z], nullptr,  row0, Bhi, Blo, 0, C);

    const int t = threadIdx.x, w = t >> 5, l = t & 31;
    const int gid = l >> 2, tig = l & 3;
    const int wm = (w & 1) * 64, wn = (w >> 1) * 32;

    #pragma unroll
    for (int i = 0; i < 4; ++i)
        #pragma unroll
        for (int j = 0; j < 4; ++j) {
            const int col = wn + 8 * j + 2 * tig;
            const int head = 2 * hp + (col >> 6), d = col & 63;
            const size_t r0 = row0 + wm + 16 * i + gid, r1 = r0 + 8;
            if (z == 2) {
                float* O = g_vh + (size_t)head * MROWS * DK;
                *(float2*)(O + r0 * DK + d) = make_float2(C[i][j][0], C[i][j][1]);
                *(float2*)(O + r1 * DK + d) = make_float2(C[i][j][2], C[i][j][3]);
            } else {
                hf* Hi = (z == 0 ? g_qhi : g_khi);
                hf* Lo = (z == 0 ? g_qlo : g_klo);
                #pragma unroll
                for (int rr = 0; rr < 2; ++rr) {
                    const size_t r = rr ? r1 : r0;
                    const float f0 = C[i][j][2 * rr], f1 = C[i][j][2 * rr + 1];
                    uint32_t hh = pack_hf(f0, f1);
                    __half2 h2 = *(__half2*)&hh;
                    uint32_t ll = pack_hf(f0 - __half2float(h2.x),
                                          f1 - __half2float(h2.y));
                    const size_t b = r >> 11, lq = r & 2047;
                    const size_t o = (((size_t)head * BB + b) * LL + lq) * DK + d;
                    *(uint32_t*)(Hi + o) = hh;
                    *(uint32_t*)(Lo + o) = ll;
                }
            }
        }
}

// ---------------------------------------------------------------------------
// Kernel: output projection + bias. grid (32, 8). A = atthi (hi only), 2-MMA.
// ---------------------------------------------------------------------------
__global__ __launch_bounds__(256, 1) void gemm_out_mma(
    const float* __restrict__ bias, float* __restrict__ out)
{
    extern __shared__ char smraw[];
    uint32_t sb = (smem_u32(smraw) + 127) & ~127u;
    const size_t row0 = (size_t)blockIdx.x * 128;
    const size_t col0 = (size_t)blockIdx.y * 128;

    float C[4][4][4] = {};
    gemm_core<false>(sb, g_atthi, nullptr, row0, g_wphi, g_wplo, col0, C);

    const int t = threadIdx.x, w = t >> 5, l = t & 31;
    const int gid = l >> 2, tig = l & 3;
    const int wm = (w & 1) * 64, wn = (w >> 1) * 32;

    #pragma unroll
    for (int i = 0; i < 4; ++i)
        #pragma unroll
        for (int j = 0; j < 4; ++j) {
            size_t col = col0 + wn + 8 * j + 2 * tig;
            size_t r = row0 + wm + 16 * i + gid;
            float2 b2 = *(const float2*)(bias + col);
            *(float2*)(out + r * DM + col) =
                make_float2(C[i][j][0] + b2.x, C[i][j][1] + b2.y);
            *(float2*)(out + (r + 8) * DM + col) =
                make_float2(C[i][j][2] + b2.x, C[i][j][3] + b2.y);
        }
}

// ---------------------------------------------------------------------------
// Flash attention on HMMA (fp16). grid (16, 32). 128 q-rows/CTA, 64-key tiles.
// QK: 3-MMA split. PV: 2-MMA (P hi only, V hi+lo). Epilogue: (o/l)*q -> fp16.
// ---------------------------------------------------------------------------
#define ATTN_SMEM (32768 + 2 * 32768 + 128)

__device__ __forceinline__ void attn_fill(uint32_t base,
    const hf* khi, const hf* klo, const hf* vthi, const hf* vtlo, int j0)
{
    const int t = threadIdx.x;
    #pragma unroll
    for (int i = 0; i < 2; ++i) {
        int g = i * 256 + t;
        int row = g >> 3, u = g & 7;
        uint32_t s = swz(row, u);
        CP16(base + s,         khi  + (size_t)(j0 + row) * DK + u * 8);
        CP16(base + 8192 + s,  klo  + (size_t)(j0 + row) * DK + u * 8);
        CP16(base + 16384 + s, vthi + (size_t)row * LL + j0 + u * 8);
        CP16(base + 24576 + s, vtlo + (size_t)row * LL + j0 + u * 8);
    }
}

__global__ __launch_bounds__(256, 1) void attn_mma()
{
    extern __shared__ char smraw[];
    const uint32_t sb = (smem_u32(smraw) + 127) & ~127u;
    const uint32_t QHI = sb, QLO = sb + 16384, ST0 = sb + 32768;

    const int hb = blockIdx.y;
    const int h = hb >> 1, b = hb & 1;
    const int l0 = blockIdx.x * 128;
    const hf* qhi = g_qhi + (size_t)hb * LL * DK;
    const hf* qlo = g_qlo + (size_t)hb * LL * DK;
    const hf* khi = g_khi + (size_t)hb * LL * DK;
    const hf* klo = g_klo + (size_t)hb * LL * DK;
    const hf* vthi = g_vthi + (size_t)hb * DK * LL;
    const hf* vtlo = g_vtlo + (size_t)hb * DK * LL;

    const int t = threadIdx.x, w = t >> 5, l = t & 31;
    const int gid = l >> 2, tig = l & 3;
    const int mi = l >> 3;

    // Load Q tile (hi+lo) into smem
    #pragma unroll
    for (int i = 0; i < 4; ++i) {
        int g = i * 256 + t;
        int row = g >> 3, u = g & 7;
        uint32_t s = swz(row, u);
        *(uint4*)(smraw + (QHI - sb) + s) =
            *(const uint4*)(qhi + (size_t)(l0 + row) * DK + u * 8);
        *(uint4*)(smraw + (QLO - sb) + s) =
            *(const uint4*)(qlo + (size_t)(l0 + row) * DK + u * 8);
    }
    attn_fill(ST0, khi, klo, vthi, vtlo, 0);
    CP_COMMIT();
    __syncthreads();

    uint32_t qfh[4][4], qfl[4][4];
    #pragma unroll
    for (int kt = 0; kt < 4; ++kt) {
        int row = w * 16 + (l & 7) + ((mi & 1) << 3);
        int u = kt * 2 + (mi >> 1);
        ldm4(qfh[kt], QHI + swz(row, u));
        ldm4(qfl[kt], QLO + swz(row, u));
    }

    float o[8][4] = {};
    float m0 = -1e30f, m1 = -1e30f, l0s = 0.f, l1s = 0.f;

    for (int jt = 0; jt < 32; ++jt) {
        if (jt + 1 < 32) {
            attn_fill(ST0 + ((jt + 1) & 1) * 32768, khi, klo, vthi, vtlo,
                      (jt + 1) * 64);
            CP_COMMIT();
            CP_WAIT1();
        } else {
            CP_WAIT0();
        }
        __syncthreads();
        const uint32_t tb = ST0 + (jt & 1) * 32768;

        // ---- S = Q K^T (3-MMA split) ----
        float s[8][4] = {};
        #pragma unroll
        for (int kt = 0; kt < 4; ++kt) {
            uint32_t kh[8][2], kl[8][2];
            #pragma unroll
            for (int jp = 0; jp < 4; ++jp) {
                int row = jp * 16 + ((mi >> 1) << 3) + (l & 7);
                int u = kt * 2 + (mi & 1);
                uint32_t r4[4];
                ldm4(r4, tb + swz(row, u));
                kh[2*jp][0] = r4[0]; kh[2*jp][1] = r4[1];
                kh[2*jp+1][0] = r4[2]; kh[2*jp+1][1] = r4[3];
                ldm4(r4, tb + 8192 + swz(row, u));
                kl[2*jp][0] = r4[0]; kl[2*jp][1] = r4[1];
                kl[2*jp+1][0] = r4[2]; kl[2*jp+1][1] = r4[3];
            }
            #pragma unroll
            for (int n = 0; n < 8; ++n) {
                mma16816(s[n], qfh[kt], kh[n]);
                mma16816(s[n], qfh[kt], kl[n]);
                mma16816(s[n], qfl[kt], kh[n]);
            }
        }

        // ---- online softmax (rows split: c0/c1 halves per thread) ----
        float rm0 = -1e30f, rm1 = -1e30f;
        #pragma unroll
        for (int n = 0; n < 8; ++n) {
            rm0 = fmaxf(rm0, fmaxf(s[n][0], s[n][1]));
            rm1 = fmaxf(rm1, fmaxf(s[n][2], s[n][3]));
        }
        rm0 = fmaxf(rm0, __shfl_xor_sync(0xffffffffu, rm0, 1));
        rm0 = fmaxf(rm0, __shfl_xor_sync(0xffffffffu, rm0, 2));
        rm1 = fmaxf(rm1, __shfl_xor_sync(0xffffffffu, rm1, 1));
        rm1 = fmaxf(rm1, __shfl_xor_sync(0xffffffffu, rm1, 2));
        const float mn0 = fmaxf(m0, rm0), mn1 = fmaxf(m1, rm1);
        const float sc0 = __expf(m0 - mn0), sc1 = __expf(m1 - mn1);
        m0 = mn0; m1 = mn1;
        float rs0 = 0.f, rs1 = 0.f;
        #pragma unroll
        for (int n = 0; n < 8; ++n) {
            s[n][0] = __expf(s[n][0] - mn0); s[n][1] = __expf(s[n][1] - mn0);
            s[n][2] = __expf(s[n][2] - mn1); s[n][3] = __expf(s[n][3] - mn1);
            rs0 += s[n][0] + s[n][1];
            rs1 += s[n][2] + s[n][3];
        }
        rs0 += __shfl_xor_sync(0xffffffffu, rs0, 1);
        rs0 += __shfl_xor_sync(0xffffffffu, rs0, 2);
        rs1 += __shfl_xor_sync(0xffffffffu, rs1, 1);
        rs1 += __shfl_xor_sync(0xffffffffu, rs1, 2);
        l0s = l0s * sc0 + rs0;
        l1s = l1s * sc1 + rs1;
        #pragma unroll
        for (int n = 0; n < 8; ++n) {
            o[n][0] *= sc0; o[n][1] *= sc0;
            o[n][2] *= sc1; o[n][3] *= sc1;
        }

        // ---- P (hi only) + PV 2-MMA ----
        #pragma unroll
        for (int kt = 0; kt < 4; ++kt) {
            uint32_t pah[4] = {
                pack_hf(s[2*kt][0],   s[2*kt][1]),
                pack_hf(s[2*kt][2],   s[2*kt][3]),
                pack_hf(s[2*kt+1][0], s[2*kt+1][1]),
                pack_hf(s[2*kt+1][2], s[2*kt+1][3]) };
            uint32_t vh[8][2], vl[8][2];
            #pragma unroll
            for (int jp = 0; jp < 4; ++jp) {
                int row = jp * 16 + ((mi >> 1) << 3) + (l & 7);
                int u = kt * 2 + (mi & 1);
                uint32_t r4[4];
                ldm4(r4, tb + 16384 + swz(row, u));
                vh[2*jp][0] = r4[0]; vh[2*jp][1] = r4[1];
                vh[2*jp+1][0] = r4[2]; vh[2*jp+1][1] = r4[3];
                ldm4(r4, tb + 24576 + swz(row, u));
                vl[2*jp][0] = r4[0]; vl[2*jp][1] = r4[1];
                vl[2*jp+1][0] = r4[2]; vl[2*jp+1][1] = r4[3];
            }
            #pragma unroll
            for (int n = 0; n < 8; ++n) {
                mma16816(o[n], pah, vh[n]);
                mma16816(o[n], pah, vl[n]);
            }
        }
        __syncthreads();
    }

    // ---- epilogue: (o / l) * q -> fp16 hi ----
    const float inv0 = 1.0f / l0s, inv1 = 1.0f / l1s;
    const size_t r0 = l0 + w * 16 + gid, r1 = r0 + 8;
    #pragma unroll
    for (int n = 0; n < 8; ++n) {
        const int d = 8 * n + 2 * tig;
        __half2 qh2a = *(const __half2*)(qhi + r0 * DK + d);
        __half2 ql2a = *(const __half2*)(qlo + r0 * DK + d);
        __half2 qh2b = *(const __half2*)(qhi + r1 * DK + d);
        __half2 ql2b = *(const __half2*)(qlo + r1 * DK + d);
        float qa0 = __half2float(qh2a.x) + __half2float(ql2a.x);
        float qa1 = __half2float(qh2a.y) + __half2float(ql2a.y);
        float qb0 = __half2float(qh2b.x) + __half2float(ql2b.x);
        float qb1 = __half2float(qh2b.y) + __half2float(ql2b.y);
        float v00 = o[n][0] * inv0 * qa0, v01 = o[n][1] * inv0 * qa1;
        float v10 = o[n][2] * inv1 * qb0, v11 = o[n][3] * inv1 * qb1;

        size_t o0 = ((size_t)b * LL + r0) * DM + h * DK + d;
        size_t o1 = ((size_t)b * LL + r1) * DM + h * DK + d;
        *(uint32_t*)(g_atthi + o0) = pack_hf(v00, v01);
        *(uint32_t*)(g_atthi + o1) = pack_hf(v10, v11);
    }
}

// ---------------------------------------------------------------------------
extern "C" void kernel_launch(void* const* d_in, const int* in_sizes, int n_in,
                              void* d_out, int out_size)
{
    const float* q  = (const float*)d_in[0];
    const float* k  = (const float*)d_in[1];
    const float* v  = (const float*)d_in[2];
    const float* wq = (const float*)d_in[3];
    const float* wk = (const float*)d_in[4];
    const float* wv = (const float*)d_in[5];
    const float* wp = (const float*)d_in[6];
    const float* bp = (const float*)d_in[7];
    float* out = (float*)d_out;

    cudaFuncSetAttribute(gemm_proj_mma,
                         cudaFuncAttributeMaxDynamicSharedMemorySize, GEMM_SMEM);
    cudaFuncSetAttribute(gemm_out_mma,
                         cudaFuncAttributeMaxDynamicSharedMemorySize, GEMM_SMEM);
    cudaFuncSetAttribute(attn_mma,
                         cudaFuncAttributeMaxDynamicSharedMemorySize, ATTN_SMEM);

    const int n4x = MROWS * DM / 4;
    const int n4w = DM * DM / 4;
    conv_split_kernel<<<(n4x + 255) / 256, 256>>>(q,  0, n4x);
    conv_split_kernel<<<(n4x + 255) / 256, 256>>>(k,  1, n4x);
    conv_split_kernel<<<(n4x + 255) / 256, 256>>>(v,  2, n4x);
    conv_split_kernel<<<(n4w + 255) / 256, 256>>>(wp, 3, n4w);
    conv_wt_kernel<<<dim3(NH, 3), 256>>>(wq, wk, wv);

    gemm_proj_mma<<<dim3(MROWS / 128, NH / 2, 3), 256, GEMM_SMEM>>>();

    conv_vt_kernel<<<dim3(LL / 64, NH * BB), 256>>>();

    attn_mma<<<dim3(LL / 128, NH * BB), 256, ATTN_SMEM>>>();

    gemm_out_mma<<<dim3(MROWS / 128, DM / 128), 256, GEMM_SMEM>>>(bp, out);
}

// round 6
// speedup vs baseline: 3.7731x; 1.0938x over previous
#include <cuda_runtime.h>
#include <cuda_fp16.h>
#include <cstdint>

#define BB 2
#define LL 2048
#define DM 1024
#define NH 16
#define DK 64
#define MROWS (BB * LL)   // 4096

typedef __half hf;

// ---------------------------------------------------------------------------
// Global scratch (no allocations allowed)
// ---------------------------------------------------------------------------
__device__ float g_vh[NH * MROWS * DK];         // fp32 V projections (pre-transpose)

__device__ hf g_xhi[3][MROWS * DM];             // split inputs q,k,v (v: hi only)
__device__ hf g_xlo[3][MROWS * DM];
__device__ hf g_wthi[3 * NH * DK * DM];         // W transposed [z][h][n][k]
__device__ hf g_wtlo[3 * NH * DK * DM];
__device__ hf g_wphi[DM * DM];                  // w_proj [n][k]
__device__ hf g_wplo[DM * DM];

__device__ hf g_qhi[NH * BB * LL * DK];         // [hb][l][k]
__device__ hf g_qlo[NH * BB * LL * DK];
__device__ hf g_khi[NH * BB * LL * DK];
__device__ hf g_klo[NH * BB * LL * DK];
__device__ hf g_vthi[NH * BB * DK * LL];        // [hb][d][l]  (V transposed, hi only)

__device__ hf g_atthi[MROWS * DM];              // attention output (hi only)

// ---------------------------------------------------------------------------
// PTX helpers (base-ISA: mma.sync / ldmatrix / cp.async)
// ---------------------------------------------------------------------------
__device__ __forceinline__ uint32_t smem_u32(const void* p) {
    uint32_t a;
    asm("{ .reg .u64 t; cvta.to.shared.u64 t, %1; cvt.u32.u64 %0, t; }"
        : "=r"(a) : "l"(p));
    return a;
}
__device__ __forceinline__ void ldm4(uint32_t r[4], uint32_t a) {
    asm volatile("ldmatrix.sync.aligned.m8n8.x4.shared.b16 {%0,%1,%2,%3}, [%4];"
        : "=r"(r[0]), "=r"(r[1]), "=r"(r[2]), "=r"(r[3]) : "r"(a));
}
__device__ __forceinline__ void mma16816(float c[4], const uint32_t a[4],
                                         const uint32_t b[2]) {
    asm volatile("mma.sync.aligned.m16n8k16.row.col.f32.f16.f16.f32 "
        "{%0,%1,%2,%3}, {%4,%5,%6,%7}, {%8,%9}, {%0,%1,%2,%3};"
        : "+f"(c[0]), "+f"(c[1]), "+f"(c[2]), "+f"(c[3])
        : "r"(a[0]), "r"(a[1]), "r"(a[2]), "r"(a[3]), "r"(b[0]), "r"(b[1]));
}
#define CP16(dst, src) \
    asm volatile("cp.async.cg.shared.global [%0], [%1], 16;" \
                 :: "r"(dst), "l"(src) : "memory")
#define CP_COMMIT() asm volatile("cp.async.commit_group;" ::: "memory")
#define CP_WAIT1()  asm volatile("cp.async.wait_group 1;" ::: "memory")
#define CP_WAIT0()  asm volatile("cp.async.wait_group 0;" ::: "memory")

// 128B-row tile swizzle: unit = 16B column, XOR by row&7 (conflict-free ldmatrix)
__device__ __forceinline__ uint32_t swz(int row, int u) {
    return (uint32_t)(row * 128 + ((u ^ (row & 7)) << 4));
}
// pack two fp32 into f16x2 (first arg -> low half)
__device__ __forceinline__ uint32_t pack_hf(float lo, float hi) {
    uint32_t r;
    asm("cvt.rn.f16x2.f32 %0, %1, %2;" : "=r"(r) : "f"(hi), "f"(lo));
    return r;
}

// ---------------------------------------------------------------------------
// Conversion kernels
// ---------------------------------------------------------------------------
__global__ void conv_split_kernel(const float* __restrict__ q,
                                  const float* __restrict__ k,
                                  const float* __restrict__ v,
                                  const float* __restrict__ wp)
{
    const int sel = blockIdx.y;
    const float* src;
    hf *hi, *lo;
    bool wlo = true;
    int n4;
    if      (sel == 0) { src = q;  hi = g_xhi[0]; lo = g_xlo[0]; n4 = MROWS * DM / 4; }
    else if (sel == 1) { src = k;  hi = g_xhi[1]; lo = g_xlo[1]; n4 = MROWS * DM / 4; }
    else if (sel == 2) { src = v;  hi = g_xhi[2]; lo = nullptr;  n4 = MROWS * DM / 4; wlo = false; }
    else               { src = wp; hi = g_wphi;   lo = g_wplo;   n4 = DM * DM / 4; }

    int i = blockIdx.x * 256 + threadIdx.x;
    if (i >= n4) return;
    float4 vv = ((const float4*)src)[i];
    uint32_t h01 = pack_hf(vv.x, vv.y);
    uint32_t h23 = pack_hf(vv.z, vv.w);
    ((uint32_t*)hi)[2 * i]     = h01;
    ((uint32_t*)hi)[2 * i + 1] = h23;
    if (wlo) {
        __half2 f01 = *(__half2*)&h01, f23 = *(__half2*)&h23;
        ((uint32_t*)lo)[2 * i] =
            pack_hf(vv.x - __half2float(f01.x), vv.y - __half2float(f01.y));
        ((uint32_t*)lo)[2 * i + 1] =
            pack_hf(vv.z - __half2float(f23.x), vv.w - __half2float(f23.y));
    }
}

// Transpose + split weights: Wt[z][h][n][k] = W_z[h][k][n], via smem transpose
__global__ void conv_wt_kernel(const float* __restrict__ wq,
                               const float* __restrict__ wk,
                               const float* __restrict__ wv)
{
    __shared__ float ts[64][65];
    const int h = blockIdx.x, z = blockIdx.y;
    const float* W = (z == 0 ? wq : z == 1 ? wk : wv) + (size_t)h * DM * DK;
    hf* hi = g_wthi + (size_t)(z * NH + h) * DK * DM;
    hf* lo = g_wtlo + (size_t)(z * NH + h) * DK * DM;
    const int t = threadIdx.x;
    for (int k0 = 0; k0 < DM; k0 += 64) {
        __syncthreads();
        for (int i = 0; i < 16; ++i) {
            int idx = i * 256 + t;
            int r = idx >> 6, c = idx & 63;
            ts[r][c] = W[(size_t)(k0 + r) * DK + c];
        }
        __syncthreads();
        for (int i = 0; i < 16; ++i) {
            int idx = i * 256 + t;
            int n = idx >> 6, c = idx & 63;
            float x = ts[c][n];
            hf h0 = __float2half_rn(x);
            hi[(size_t)n * DM + k0 + c] = h0;
            lo[(size_t)n * DM + k0 + c] = __float2half_rn(x - __half2float(h0));
        }
    }
}

// g_vh [hb][l][d] -> transposed g_vthi [hb][d][l] (hi only)
__global__ void conv_vt_kernel()
{
    __shared__ float ts[64][65];
    const int hb = blockIdx.y;
    const int l0 = blockIdx.x * 64;
    const float* src = g_vh + (size_t)hb * LL * DK;
    const int t = threadIdx.x;
    for (int i = 0; i < 16; ++i) {
        int idx = i * 256 + t;
        int r = idx >> 6, d = idx & 63;
        ts[r][d] = src[(size_t)(l0 + r) * DK + d];
    }
    __syncthreads();
    for (int i = 0; i < 16; ++i) {
        int idx = i * 256 + t;
        int d = idx >> 6, c = idx & 63;
        g_vthi[((size_t)hb * DK + d) * LL + l0 + c] = __float2half_rn(ts[c][d]);
    }
}

// ---------------------------------------------------------------------------
// GEMM core: C[128x128] (fp32 frags) = A[128,1024] @ B[128,1024]^T
// USE_ALO: 3-MMA split; else 2-MMA. cp.async double-buffered 64-K chunks.
// ---------------------------------------------------------------------------
#define GEMM_SMEM (2 * 65536 + 128)

template <bool USE_ALO>
__device__ __forceinline__ void gemm_fill(uint32_t base,
    const hf* __restrict__ Ahi, const hf* __restrict__ Alo, size_t ar0,
    const hf* __restrict__ Bhi, const hf* __restrict__ Blo, size_t br0,
    int k0)
{
    const int t = threadIdx.x;
    #pragma unroll
    for (int i = 0; i < 4; ++i) {
        int g = i * 256 + t;
        int row = g >> 3, u = g & 7;
        size_t goff = (size_t)row * DM + k0 + u * 8;
        uint32_t s = swz(row, u);
        CP16(base + s, Ahi + (size_t)ar0 * DM + goff);
        if (USE_ALO) CP16(base + 16384 + s, Alo + (size_t)ar0 * DM + goff);
        CP16(base + 32768 + s, Bhi + (size_t)br0 * DM + goff);
        CP16(base + 49152 + s, Blo + (size_t)br0 * DM + goff);
    }
}

template <bool USE_ALO>
__device__ __forceinline__ void gemm_core(uint32_t sb,
    const hf* Ahi, const hf* Alo, size_t ar0,
    const hf* Bhi, const hf* Blo, size_t br0,
    float C[4][4][4])
{
    const int t = threadIdx.x, w = t >> 5, l = t & 31;
    const int wm = (w & 1) * 64, wn = (w >> 1) * 32;
    const int mi = l >> 3;

    gemm_fill<USE_ALO>(sb, Ahi, Alo, ar0, Bhi, Blo, br0, 0);
    CP_COMMIT();

    for (int c = 0; c < 16; ++c) {
        if (c + 1 < 16) {
            gemm_fill<USE_ALO>(sb + ((c + 1) & 1) * 65536, Ahi, Alo, ar0,
                               Bhi, Blo, br0, (c + 1) * 64);
            CP_COMMIT();
            CP_WAIT1();
        } else {
            CP_WAIT0();
        }
        __syncthreads();
        const uint32_t tb = sb + (c & 1) * 65536;

        #pragma unroll
        for (int kt = 0; kt < 4; ++kt) {
            uint32_t ahi[4][4], alo[4][4];
            #pragma unroll
            for (int i = 0; i < 4; ++i) {
                int row = wm + 16 * i + (l & 7) + ((mi & 1) << 3);
                int u = kt * 2 + (mi >> 1);
                ldm4(ahi[i], tb + swz(row, u));
                if (USE_ALO) ldm4(alo[i], tb + 16384 + swz(row, u));
            }
            uint32_t bhi[4][2], blo[4][2];
            #pragma unroll
            for (int jp = 0; jp < 2; ++jp) {
                int row = wn + jp * 16 + ((mi >> 1) << 3) + (l & 7);
                int u = kt * 2 + (mi & 1);
                uint32_t r4[4];
                ldm4(r4, tb + 32768 + swz(row, u));
                bhi[2*jp][0] = r4[0]; bhi[2*jp][1] = r4[1];
                bhi[2*jp+1][0] = r4[2]; bhi[2*jp+1][1] = r4[3];
                ldm4(r4, tb + 49152 + swz(row, u));
                blo[2*jp][0] = r4[0]; blo[2*jp][1] = r4[1];
                blo[2*jp+1][0] = r4[2]; blo[2*jp+1][1] = r4[3];
            }
            #pragma unroll
            for (int i = 0; i < 4; ++i)
                #pragma unroll
                for (int j = 0; j < 4; ++j) {
                    mma16816(C[i][j], ahi[i], bhi[j]);
                    mma16816(C[i][j], ahi[i], blo[j]);
                    if (USE_ALO) mma16816(C[i][j], alo[i], bhi[j]);
                }
        }
        __syncthreads();
    }
}

// ---------------------------------------------------------------------------
// Kernel: per-head-pair input projections. grid (32, 8, 3)
// ---------------------------------------------------------------------------
__global__ __launch_bounds__(256, 1) void gemm_proj_mma()
{
    extern __shared__ char smraw[];
    uint32_t sb = (smem_u32(smraw) + 127) & ~127u;
    const int z = blockIdx.z, hp = blockIdx.y;
    const size_t row0 = (size_t)blockIdx.x * 128;

    float C[4][4][4] = {};
    const hf* Bhi = g_wthi + (size_t)(z * NH + 2 * hp) * DK * DM;
    const hf* Blo = g_wtlo + (size_t)(z * NH + 2 * hp) * DK * DM;
    if (z < 2)
        gemm_core<true >(sb, g_xhi[z], g_xlo[z], row0, Bhi, Blo, 0, C);
    else
        gemm_core<false>(sb, g_xhi[z], nullptr,  row0, Bhi, Blo, 0, C);

    const int t = threadIdx.x, w = t >> 5, l = t & 31;
    const int gid = l >> 2, tig = l & 3;
    const int wm = (w & 1) * 64, wn = (w >> 1) * 32;

    #pragma unroll
    for (int i = 0; i < 4; ++i)
        #pragma unroll
        for (int j = 0; j < 4; ++j) {
            const int col = wn + 8 * j + 2 * tig;
            const int head = 2 * hp + (col >> 6), d = col & 63;
            const size_t r0 = row0 + wm + 16 * i + gid, r1 = r0 + 8;
            if (z == 2) {
                float* O = g_vh + (size_t)head * MROWS * DK;
                *(float2*)(O + r0 * DK + d) = make_float2(C[i][j][0], C[i][j][1]);
                *(float2*)(O + r1 * DK + d) = make_float2(C[i][j][2], C[i][j][3]);
            } else {
                hf* Hi = (z == 0 ? g_qhi : g_khi);
                hf* Lo = (z == 0 ? g_qlo : g_klo);
                #pragma unroll
                for (int rr = 0; rr < 2; ++rr) {
                    const size_t r = rr ? r1 : r0;
                    const float f0 = C[i][j][2 * rr], f1 = C[i][j][2 * rr + 1];
                    uint32_t hh = pack_hf(f0, f1);
                    __half2 h2 = *(__half2*)&hh;
                    uint32_t ll = pack_hf(f0 - __half2float(h2.x),
                                          f1 - __half2float(h2.y));
                    const size_t b = r >> 11, lq = r & 2047;
                    const size_t o = (((size_t)head * BB + b) * LL + lq) * DK + d;
                    *(uint32_t*)(Hi + o) = hh;
                    *(uint32_t*)(Lo + o) = ll;
                }
            }
        }
}

// ---------------------------------------------------------------------------
// Kernel: output projection + bias. grid (32, 8). 2-MMA.
// ---------------------------------------------------------------------------
__global__ __launch_bounds__(256, 1) void gemm_out_mma(
    const float* __restrict__ bias, float* __restrict__ out)
{
    extern __shared__ char smraw[];
    uint32_t sb = (smem_u32(smraw) + 127) & ~127u;
    const size_t row0 = (size_t)blockIdx.x * 128;
    const size_t col0 = (size_t)blockIdx.y * 128;

    float C[4][4][4] = {};
    gemm_core<false>(sb, g_atthi, nullptr, row0, g_wphi, g_wplo, col0, C);

    const int t = threadIdx.x, w = t >> 5, l = t & 31;
    const int gid = l >> 2, tig = l & 3;
    const int wm = (w & 1) * 64, wn = (w >> 1) * 32;

    #pragma unroll
    for (int i = 0; i < 4; ++i)
        #pragma unroll
        for (int j = 0; j < 4; ++j) {
            size_t col = col0 + wn + 8 * j + 2 * tig;
            size_t r = row0 + wm + 16 * i + gid;
            float2 b2 = *(const float2*)(bias + col);
            *(float2*)(out + r * DM + col) =
                make_float2(C[i][j][0] + b2.x, C[i][j][1] + b2.y);
            *(float2*)(out + (r + 8) * DM + col) =
                make_float2(C[i][j][2] + b2.x, C[i][j][3] + b2.y);
        }
}

// ---------------------------------------------------------------------------
// Flash attention on HMMA (fp16). grid (16, 32). 128 q-rows/CTA, 64-key tiles.
// QK: 3-MMA split. PV: 1-MMA (P hi x V hi). Stage = K hi/lo + V hi = 24 KB.
// Target 2 CTAs/SM: smem 82 KB, launch_bounds(256, 2).
// ---------------------------------------------------------------------------
#define ATTN_STAGE 24576
#define ATTN_SMEM (32768 + 2 * ATTN_STAGE + 128)

__device__ __forceinline__ void attn_fill(uint32_t base,
    const hf* khi, const hf* klo, const hf* vthi, int j0)
{
    const int t = threadIdx.x;
    #pragma unroll
    for (int i = 0; i < 2; ++i) {
        int g = i * 256 + t;
        int row = g >> 3, u = g & 7;
        uint32_t s = swz(row, u);
        CP16(base + s,         khi  + (size_t)(j0 + row) * DK + u * 8);
        CP16(base + 8192 + s,  klo  + (size_t)(j0 + row) * DK + u * 8);
        CP16(base + 16384 + s, vthi + (size_t)row * LL + j0 + u * 8);
    }
}

__global__ __launch_bounds__(256, 2) void attn_mma()
{
    extern __shared__ char smraw[];
    const uint32_t sb = (smem_u32(smraw) + 127) & ~127u;
    const uint32_t QHI = sb, QLO = sb + 16384, ST0 = sb + 32768;

    const int hb = blockIdx.y;
    const int h = hb >> 1, b = hb & 1;
    const int l0 = blockIdx.x * 128;
    const hf* qhi = g_qhi + (size_t)hb * LL * DK;
    const hf* qlo = g_qlo + (size_t)hb * LL * DK;
    const hf* khi = g_khi + (size_t)hb * LL * DK;
    const hf* klo = g_klo + (size_t)hb * LL * DK;
    const hf* vthi = g_vthi + (size_t)hb * DK * LL;

    const int t = threadIdx.x, w = t >> 5, l = t & 31;
    const int gid = l >> 2, tig = l & 3;
    const int mi = l >> 3;

    // Load Q tile (hi+lo) into smem
    #pragma unroll
    for (int i = 0; i < 4; ++i) {
        int g = i * 256 + t;
        int row = g >> 3, u = g & 7;
        uint32_t s = swz(row, u);
        *(uint4*)(smraw + (QHI - sb) + s) =
            *(const uint4*)(qhi + (size_t)(l0 + row) * DK + u * 8);
        *(uint4*)(smraw + (QLO - sb) + s) =
            *(const uint4*)(qlo + (size_t)(l0 + row) * DK + u * 8);
    }
    attn_fill(ST0, khi, klo, vthi, 0);
    CP_COMMIT();
    __syncthreads();

    // Q hi fragments resident; Q lo fetched on demand (register pressure)
    uint32_t qfh[4][4];
    #pragma unroll
    for (int kt = 0; kt < 4; ++kt) {
        int row = w * 16 + (l & 7) + ((mi & 1) << 3);
        int u = kt * 2 + (mi >> 1);
        ldm4(qfh[kt], QHI + swz(row, u));
    }

    float o[8][4] = {};
    float m0 = -1e30f, m1 = -1e30f, l0s = 0.f, l1s = 0.f;

    for (int jt = 0; jt < 32; ++jt) {
        if (jt + 1 < 32) {
            attn_fill(ST0 + ((jt + 1) & 1) * ATTN_STAGE, khi, klo, vthi,
                      (jt + 1) * 64);
            CP_COMMIT();
            CP_WAIT1();
        } else {
            CP_WAIT0();
        }
        __syncthreads();
        const uint32_t tb = ST0 + (jt & 1) * ATTN_STAGE;

        // ---- S = Q K^T (3-MMA split) ----
        float s[8][4] = {};
        #pragma unroll
        for (int kt = 0; kt < 4; ++kt) {
            uint32_t qfl[4];
            {
                int row = w * 16 + (l & 7) + ((mi & 1) << 3);
                int u = kt * 2 + (mi >> 1);
                ldm4(qfl, QLO + swz(row, u));
            }
            uint32_t kh[8][2], kl[8][2];
            #pragma unroll
            for (int jp = 0; jp < 4; ++jp) {
                int row = jp * 16 + ((mi >> 1) << 3) + (l & 7);
                int u = kt * 2 + (mi & 1);
                uint32_t r4[4];
                ldm4(r4, tb + swz(row, u));
                kh[2*jp][0] = r4[0]; kh[2*jp][1] = r4[1];
                kh[2*jp+1][0] = r4[2]; kh[2*jp+1][1] = r4[3];
                ldm4(r4, tb + 8192 + swz(row, u));
                kl[2*jp][0] = r4[0]; kl[2*jp][1] = r4[1];
                kl[2*jp+1][0] = r4[2]; kl[2*jp+1][1] = r4[3];
            }
            #pragma unroll
            for (int n = 0; n < 8; ++n) {
                mma16816(s[n], qfh[kt], kh[n]);
                mma16816(s[n], qfh[kt], kl[n]);
                mma16816(s[n], qfl,     kh[n]);
            }
        }

        // ---- online softmax ----
        float rm0 = -1e30f, rm1 = -1e30f;
        #pragma unroll
        for (int n = 0; n < 8; ++n) {
            rm0 = fmaxf(rm0, fmaxf(s[n][0], s[n][1]));
            rm1 = fmaxf(rm1, fmaxf(s[n][2], s[n][3]));
        }
        rm0 = fmaxf(rm0, __shfl_xor_sync(0xffffffffu, rm0, 1));
        rm0 = fmaxf(rm0, __shfl_xor_sync(0xffffffffu, rm0, 2));
        rm1 = fmaxf(rm1, __shfl_xor_sync(0xffffffffu, rm1, 1));
        rm1 = fmaxf(rm1, __shfl_xor_sync(0xffffffffu, rm1, 2));
        const float mn0 = fmaxf(m0, rm0), mn1 = fmaxf(m1, rm1);
        const float sc0 = __expf(m0 - mn0), sc1 = __expf(m1 - mn1);
        m0 = mn0; m1 = mn1;
        float rs0 = 0.f, rs1 = 0.f;
        #pragma unroll
        for (int n = 0; n < 8; ++n) {
            s[n][0] = __expf(s[n][0] - mn0); s[n][1] = __expf(s[n][1] - mn0);
            s[n][2] = __expf(s[n][2] - mn1); s[n][3] = __expf(s[n][3] - mn1);
            rs0 += s[n][0] + s[n][1];
            rs1 += s[n][2] + s[n][3];
        }
        rs0 += __shfl_xor_sync(0xffffffffu, rs0, 1);
        rs0 += __shfl_xor_sync(0xffffffffu, rs0, 2);
        rs1 += __shfl_xor_sync(0xffffffffu, rs1, 1);
        rs1 += __shfl_xor_sync(0xffffffffu, rs1, 2);
        l0s = l0s * sc0 + rs0;
        l1s = l1s * sc1 + rs1;
        #pragma unroll
        for (int n = 0; n < 8; ++n) {
            o[n][0] *= sc0; o[n][1] *= sc0;
            o[n][2] *= sc1; o[n][3] *= sc1;
        }

        // ---- P (hi) x V (hi): 1 MMA ----
        #pragma unroll
        for (int kt = 0; kt < 4; ++kt) {
            uint32_t pah[4] = {
                pack_hf(s[2*kt][0],   s[2*kt][1]),
                pack_hf(s[2*kt][2],   s[2*kt][3]),
                pack_hf(s[2*kt+1][0], s[2*kt+1][1]),
                pack_hf(s[2*kt+1][2], s[2*kt+1][3]) };
            uint32_t vh[8][2];
            #pragma unroll
            for (int jp = 0; jp < 4; ++jp) {
                int row = jp * 16 + ((mi >> 1) << 3) + (l & 7);
                int u = kt * 2 + (mi & 1);
                uint32_t r4[4];
                ldm4(r4, tb + 16384 + swz(row, u));
                vh[2*jp][0] = r4[0]; vh[2*jp][1] = r4[1];
                vh[2*jp+1][0] = r4[2]; vh[2*jp+1][1] = r4[3];
            }
            #pragma unroll
            for (int n = 0; n < 8; ++n)
                mma16816(o[n], pah, vh[n]);
        }
        __syncthreads();
    }

    // ---- epilogue: (o / l) * q -> fp16 hi ----
    const float inv0 = 1.0f / l0s, inv1 = 1.0f / l1s;
    const size_t r0 = l0 + w * 16 + gid, r1 = r0 + 8;
    #pragma unroll
    for (int n = 0; n < 8; ++n) {
        const int d = 8 * n + 2 * tig;
        __half2 qh2a = *(const __half2*)(qhi + r0 * DK + d);
        __half2 ql2a = *(const __half2*)(qlo + r0 * DK + d);
        __half2 qh2b = *(const __half2*)(qhi + r1 * DK + d);
        __half2 ql2b = *(const __half2*)(qlo + r1 * DK + d);
        float qa0 = __half2float(qh2a.x) + __half2float(ql2a.x);
        float qa1 = __half2float(qh2a.y) + __half2float(ql2a.y);
        float qb0 = __half2float(qh2b.x) + __half2float(ql2b.x);
        float qb1 = __half2float(qh2b.y) + __half2float(ql2b.y);
        float v00 = o[n][0] * inv0 * qa0, v01 = o[n][1] * inv0 * qa1;
        float v10 = o[n][2] * inv1 * qb0, v11 = o[n][3] * inv1 * qb1;

        size_t o0 = ((size_t)b * LL + r0) * DM + h * DK + d;
        size_t o1 = ((size_t)b * LL + r1) * DM + h * DK + d;
        *(uint32_t*)(g_atthi + o0) = pack_hf(v00, v01);
        *(uint32_t*)(g_atthi + o1) = pack_hf(v10, v11);
    }
}

// ---------------------------------------------------------------------------
extern "C" void kernel_launch(void* const* d_in, const int* in_sizes, int n_in,
                              void* d_out, int out_size)
{
    const float* q  = (const float*)d_in[0];
    const float* k  = (const float*)d_in[1];
    const float* v  = (const float*)d_in[2];
    const float* wq = (const float*)d_in[3];
    const float* wk = (const float*)d_in[4];
    const float* wv = (const float*)d_in[5];
    const float* wp = (const float*)d_in[6];
    const float* bp = (const float*)d_in[7];
    float* out = (float*)d_out;

    cudaFuncSetAttribute(gemm_proj_mma,
                         cudaFuncAttributeMaxDynamicSharedMemorySize, GEMM_SMEM);
    cudaFuncSetAttribute(gemm_out_mma,
                         cudaFuncAttributeMaxDynamicSharedMemorySize, GEMM_SMEM);
    cudaFuncSetAttribute(attn_mma,
                         cudaFuncAttributeMaxDynamicSharedMemorySize, ATTN_SMEM);

    const int n4x = MROWS * DM / 4;
    conv_split_kernel<<<dim3((n4x + 255) / 256, 4), 256>>>(q, k, v, wp);
    conv_wt_kernel<<<dim3(NH, 3), 256>>>(wq, wk, wv);

    gemm_proj_mma<<<dim3(MROWS / 128, NH / 2, 3), 256, GEMM_SMEM>>>();

    conv_vt_kernel<<<dim3(LL / 64, NH * BB), 256>>>();

    attn_mma<<<dim3(LL / 128, NH * BB), 256, ATTN_SMEM>>>();

    gemm_out_mma<<<dim3(MROWS / 128, DM / 128), 256, GEMM_SMEM>>>(bp, out);
}

// round 7
// speedup vs baseline: 3.9244x; 1.0401x over previous
#include <cuda_runtime.h>
#include <cuda_fp16.h>
#include <cstdint>

#define BB 2
#define LL 2048
#define DM 1024
#define NH 16
#define DK 64
#define MROWS (BB * LL)   // 4096

typedef __half hf;

// ---------------------------------------------------------------------------
// Global scratch (no allocations allowed)
// ---------------------------------------------------------------------------
__device__ hf g_xhi[3][MROWS * DM];             // split inputs q,k,v (v: hi only)
__device__ hf g_xlo[3][MROWS * DM];
__device__ hf g_wthi[3 * NH * DK * DM];         // W transposed [z][h][n][k]
__device__ hf g_wtlo[3 * NH * DK * DM];
__device__ hf g_wphi[DM * DM];                  // w_proj [n][k]
__device__ hf g_wplo[DM * DM];

__device__ hf g_qhi[NH * BB * LL * DK];         // [hb][l][k]
__device__ hf g_qlo[NH * BB * LL * DK];
__device__ hf g_khi[NH * BB * LL * DK];
__device__ hf g_klo[NH * BB * LL * DK];
__device__ hf g_vthi[NH * BB * DK * LL];        // [hb][d][l]  (V transposed, hi only)

__device__ hf g_atthi[MROWS * DM];              // attention output (hi only)

// ---------------------------------------------------------------------------
// PTX helpers (base-ISA: mma.sync / ldmatrix / cp.async)
// ---------------------------------------------------------------------------
__device__ __forceinline__ uint32_t smem_u32(const void* p) {
    uint32_t a;
    asm("{ .reg .u64 t; cvta.to.shared.u64 t, %1; cvt.u32.u64 %0, t; }"
        : "=r"(a) : "l"(p));
    return a;
}
__device__ __forceinline__ void ldm4(uint32_t r[4], uint32_t a) {
    asm volatile("ldmatrix.sync.aligned.m8n8.x4.shared.b16 {%0,%1,%2,%3}, [%4];"
        : "=r"(r[0]), "=r"(r[1]), "=r"(r[2]), "=r"(r[3]) : "r"(a));
}
__device__ __forceinline__ void mma16816(float c[4], const uint32_t a[4],
                                         const uint32_t b[2]) {
    asm volatile("mma.sync.aligned.m16n8k16.row.col.f32.f16.f16.f32 "
        "{%0,%1,%2,%3}, {%4,%5,%6,%7}, {%8,%9}, {%0,%1,%2,%3};"
        : "+f"(c[0]), "+f"(c[1]), "+f"(c[2]), "+f"(c[3])
        : "r"(a[0]), "r"(a[1]), "r"(a[2]), "r"(a[3]), "r"(b[0]), "r"(b[1]));
}
#define CP16(dst, src) \
    asm volatile("cp.async.cg.shared.global [%0], [%1], 16;" \
                 :: "r"(dst), "l"(src) : "memory")
#define CP_COMMIT() asm volatile("cp.async.commit_group;" ::: "memory")
#define CP_WAIT1()  asm volatile("cp.async.wait_group 1;" ::: "memory")
#define CP_WAIT0()  asm volatile("cp.async.wait_group 0;" ::: "memory")

// 128B-row tile swizzle: unit = 16B column, XOR by row&7 (conflict-free ldmatrix)
__device__ __forceinline__ uint32_t swz(int row, int u) {
    return (uint32_t)(row * 128 + ((u ^ (row & 7)) << 4));
}
// pack two fp32 into f16x2 (first arg -> low half)
__device__ __forceinline__ uint32_t pack_hf(float lo, float hi) {
    uint32_t r;
    asm("cvt.rn.f16x2.f32 %0, %1, %2;" : "=r"(r) : "f"(hi), "f"(lo));
    return r;
}

// ---------------------------------------------------------------------------
// Conversion kernels
// ---------------------------------------------------------------------------
__global__ void conv_split_kernel(const float* __restrict__ q,
                                  const float* __restrict__ k,
                                  const float* __restrict__ v,
                                  const float* __restrict__ wp)
{
    const int sel = blockIdx.y;
    const float* src;
    hf *hi, *lo;
    bool wlo = true;
    int n4;
    if      (sel == 0) { src = q;  hi = g_xhi[0]; lo = g_xlo[0]; n4 = MROWS * DM / 4; }
    else if (sel == 1) { src = k;  hi = g_xhi[1]; lo = g_xlo[1]; n4 = MROWS * DM / 4; }
    else if (sel == 2) { src = v;  hi = g_xhi[2]; lo = nullptr;  n4 = MROWS * DM / 4; wlo = false; }
    else               { src = wp; hi = g_wphi;   lo = g_wplo;   n4 = DM * DM / 4; }

    int i = blockIdx.x * 256 + threadIdx.x;
    if (i >= n4) return;
    float4 vv = ((const float4*)src)[i];
    uint32_t h01 = pack_hf(vv.x, vv.y);
    uint32_t h23 = pack_hf(vv.z, vv.w);
    ((uint32_t*)hi)[2 * i]     = h01;
    ((uint32_t*)hi)[2 * i + 1] = h23;
    if (wlo) {
        __half2 f01 = *(__half2*)&h01, f23 = *(__half2*)&h23;
        ((uint32_t*)lo)[2 * i] =
            pack_hf(vv.x - __half2float(f01.x), vv.y - __half2float(f01.y));
        ((uint32_t*)lo)[2 * i + 1] =
            pack_hf(vv.z - __half2float(f23.x), vv.w - __half2float(f23.y));
    }
}

// Transpose + split weights: Wt[z][h][n][k] = W_z[h][k][n], via smem transpose
__global__ void conv_wt_kernel(const float* __restrict__ wq,
                               const float* __restrict__ wk,
                               const float* __restrict__ wv)
{
    __shared__ float ts[64][65];
    const int h = blockIdx.x, z = blockIdx.y;
    const float* W = (z == 0 ? wq : z == 1 ? wk : wv) + (size_t)h * DM * DK;
    hf* hi = g_wthi + (size_t)(z * NH + h) * DK * DM;
    hf* lo = g_wtlo + (size_t)(z * NH + h) * DK * DM;
    const int t = threadIdx.x;
    for (int k0 = 0; k0 < DM; k0 += 64) {
        __syncthreads();
        for (int i = 0; i < 16; ++i) {
            int idx = i * 256 + t;
            int r = idx >> 6, c = idx & 63;
            ts[r][c] = W[(size_t)(k0 + r) * DK + c];
        }
        __syncthreads();
        for (int i = 0; i < 16; ++i) {
            int idx = i * 256 + t;
            int n = idx >> 6, c = idx & 63;
            float x = ts[c][n];
            hf h0 = __float2half_rn(x);
            hi[(size_t)n * DM + k0 + c] = h0;
            lo[(size_t)n * DM + k0 + c] = __float2half_rn(x - __half2float(h0));
        }
    }
}

// ---------------------------------------------------------------------------
// GEMM core: C[128x128] (fp32 frags) = A[128,1024] @ B[128,1024]^T
// USE_ALO: 3-MMA split; else 2-MMA. Single 64KB stage, 2 CTAs/SM:
// the co-resident CTA hides this CTA's fill latency.
// ---------------------------------------------------------------------------
#define GEMM_SMEM (65536 + 128)

template <bool USE_ALO>
__device__ __forceinline__ void gemm_fill(uint32_t base,
    const hf* __restrict__ Ahi, const hf* __restrict__ Alo, size_t ar0,
    const hf* __restrict__ Bhi, const hf* __restrict__ Blo, size_t br0,
    int k0)
{
    const int t = threadIdx.x;
    #pragma unroll
    for (int i = 0; i < 4; ++i) {
        int g = i * 256 + t;
        int row = g >> 3, u = g & 7;
        size_t goff = (size_t)row * DM + k0 + u * 8;
        uint32_t s = swz(row, u);
        CP16(base + s, Ahi + (size_t)ar0 * DM + goff);
        if (USE_ALO) CP16(base + 16384 + s, Alo + (size_t)ar0 * DM + goff);
        CP16(base + 32768 + s, Bhi + (size_t)br0 * DM + goff);
        CP16(base + 49152 + s, Blo + (size_t)br0 * DM + goff);
    }
}

template <bool USE_ALO>
__device__ __forceinline__ void gemm_core(uint32_t sb,
    const hf* Ahi, const hf* Alo, size_t ar0,
    const hf* Bhi, const hf* Blo, size_t br0,
    float C[4][4][4])
{
    const int t = threadIdx.x, w = t >> 5, l = t & 31;
    const int wm = (w & 1) * 64, wn = (w >> 1) * 32;
    const int mi = l >> 3;

    gemm_fill<USE_ALO>(sb, Ahi, Alo, ar0, Bhi, Blo, br0, 0);
    CP_COMMIT();

    for (int c = 0; c < 16; ++c) {
        CP_WAIT0();
        __syncthreads();

        #pragma unroll
        for (int kt = 0; kt < 4; ++kt) {
            uint32_t ahi[4][4], alo[4][4];
            #pragma unroll
            for (int i = 0; i < 4; ++i) {
                int row = wm + 16 * i + (l & 7) + ((mi & 1) << 3);
                int u = kt * 2 + (mi >> 1);
                ldm4(ahi[i], sb + swz(row, u));
                if (USE_ALO) ldm4(alo[i], sb + 16384 + swz(row, u));
            }
            uint32_t bhi[4][2], blo[4][2];
            #pragma unroll
            for (int jp = 0; jp < 2; ++jp) {
                int row = wn + jp * 16 + ((mi >> 1) << 3) + (l & 7);
                int u = kt * 2 + (mi & 1);
                uint32_t r4[4];
                ldm4(r4, sb + 32768 + swz(row, u));
                bhi[2*jp][0] = r4[0]; bhi[2*jp][1] = r4[1];
                bhi[2*jp+1][0] = r4[2]; bhi[2*jp+1][1] = r4[3];
                ldm4(r4, sb + 49152 + swz(row, u));
                blo[2*jp][0] = r4[0]; blo[2*jp][1] = r4[1];
                blo[2*jp+1][0] = r4[2]; blo[2*jp+1][1] = r4[3];
            }
            #pragma unroll
            for (int i = 0; i < 4; ++i)
                #pragma unroll
                for (int j = 0; j < 4; ++j) {
                    mma16816(C[i][j], ahi[i], bhi[j]);
                    mma16816(C[i][j], ahi[i], blo[j]);
                    if (USE_ALO) mma16816(C[i][j], alo[i], bhi[j]);
                }
        }
        __syncthreads();
        if (c + 1 < 16) {
            gemm_fill<USE_ALO>(sb, Ahi, Alo, ar0, Bhi, Blo, br0, (c + 1) * 64);
            CP_COMMIT();
        }
    }
}

// ---------------------------------------------------------------------------
// Kernel: per-head-pair input projections. grid (32, 8, 3), 2 CTAs/SM.
// z=0/1 (q/k): 3-MMA, epilogue -> fp16 hi/lo split.
// z=2 (v): 2-MMA, epilogue -> fused transpose+convert into g_vthi [hb][d][l].
// ---------------------------------------------------------------------------
__global__ __launch_bounds__(256, 2) void gemm_proj_mma()
{
    extern __shared__ char smraw[];
    uint32_t sb = (smem_u32(smraw) + 127) & ~127u;
    const int z = blockIdx.z, hp = blockIdx.y;
    const size_t row0 = (size_t)blockIdx.x * 128;

    float C[4][4][4] = {};
    const hf* Bhi = g_wthi + (size_t)(z * NH + 2 * hp) * DK * DM;
    const hf* Blo = g_wtlo + (size_t)(z * NH + 2 * hp) * DK * DM;
    if (z < 2)
        gemm_core<true >(sb, g_xhi[z], g_xlo[z], row0, Bhi, Blo, 0, C);
    else
        gemm_core<false>(sb, g_xhi[z], nullptr,  row0, Bhi, Blo, 0, C);

    const int t = threadIdx.x, w = t >> 5, l = t & 31;
    const int gid = l >> 2, tig = l & 3;
    const int wm = (w & 1) * 64, wn = (w >> 1) * 32;

    #pragma unroll
    for (int i = 0; i < 4; ++i)
        #pragma unroll
        for (int j = 0; j < 4; ++j) {
            const int col = wn + 8 * j + 2 * tig;
            const int head = 2 * hp + (col >> 6), d = col & 63;
            const size_t r0 = row0 + wm + 16 * i + gid, r1 = r0 + 8;
            const size_t b = r0 >> 11;             // r0, r1 share the same b
            const size_t hb = (size_t)head * BB + b;
            if (z == 2) {
                // fused transpose+convert: g_vthi[hb][d][l]
                const size_t lq0 = r0 & 2047, lq1 = r1 & 2047;
                hf* V = g_vthi + hb * (size_t)DK * LL;
                V[(size_t)d * LL + lq0]       = __float2half_rn(C[i][j][0]);
                V[(size_t)(d + 1) * LL + lq0] = __float2half_rn(C[i][j][1]);
                V[(size_t)d * LL + lq1]       = __float2half_rn(C[i][j][2]);
                V[(size_t)(d + 1) * LL + lq1] = __float2half_rn(C[i][j][3]);
            } else {
                hf* Hi = (z == 0 ? g_qhi : g_khi);
                hf* Lo = (z == 0 ? g_qlo : g_klo);
                #pragma unroll
                for (int rr = 0; rr < 2; ++rr) {
                    const size_t r = rr ? r1 : r0;
                    const float f0 = C[i][j][2 * rr], f1 = C[i][j][2 * rr + 1];
                    uint32_t hh = pack_hf(f0, f1);
                    __half2 h2 = *(__half2*)&hh;
                    uint32_t ll = pack_hf(f0 - __half2float(h2.x),
                                          f1 - __half2float(h2.y));
                    const size_t o = (hb * LL + (r & 2047)) * DK + d;
                    *(uint32_t*)(Hi + o) = hh;
                    *(uint32_t*)(Lo + o) = ll;
                }
            }
        }
}

// ---------------------------------------------------------------------------
// Kernel: output projection + bias. grid (32, 8). 2-MMA, 2 CTAs/SM.
// ---------------------------------------------------------------------------
__global__ __launch_bounds__(256, 2) void gemm_out_mma(
    const float* __restrict__ bias, float* __restrict__ out)
{
    extern __shared__ char smraw[];
    uint32_t sb = (smem_u32(smraw) + 127) & ~127u;
    const size_t row0 = (size_t)blockIdx.x * 128;
    const size_t col0 = (size_t)blockIdx.y * 128;

    float C[4][4][4] = {};
    gemm_core<false>(sb, g_atthi, nullptr, row0, g_wphi, g_wplo, col0, C);

    const int t = threadIdx.x, w = t >> 5, l = t & 31;
    const int gid = l >> 2, tig = l & 3;
    const int wm = (w & 1) * 64, wn = (w >> 1) * 32;

    #pragma unroll
    for (int i = 0; i < 4; ++i)
        #pragma unroll
        for (int j = 0; j < 4; ++j) {
            size_t col = col0 + wn + 8 * j + 2 * tig;
            size_t r = row0 + wm + 16 * i + gid;
            float2 b2 = *(const float2*)(bias + col);
            *(float2*)(out + r * DM + col) =
                make_float2(C[i][j][0] + b2.x, C[i][j][1] + b2.y);
            *(float2*)(out + (r + 8) * DM + col) =
                make_float2(C[i][j][2] + b2.x, C[i][j][3] + b2.y);
        }
}

// ---------------------------------------------------------------------------
// Flash attention on HMMA (fp16). grid (16, 32). 128 q-rows/CTA, 64-key tiles.
// QK: 3-MMA split. PV: 1-MMA (P hi x V hi). 2 CTAs/SM, double-buffered stages.
// ---------------------------------------------------------------------------
#define ATTN_STAGE 24576
#define ATTN_SMEM (32768 + 2 * ATTN_STAGE + 128)

__device__ __forceinline__ void attn_fill(uint32_t base,
    const hf* khi, const hf* klo, const hf* vthi, int j0)
{
    const int t = threadIdx.x;
    #pragma unroll
    for (int i = 0; i < 2; ++i) {
        int g = i * 256 + t;
        int row = g >> 3, u = g & 7;
        uint32_t s = swz(row, u);
        CP16(base + s,         khi  + (size_t)(j0 + row) * DK + u * 8);
        CP16(base + 8192 + s,  klo  + (size_t)(j0 + row) * DK + u * 8);
        CP16(base + 16384 + s, vthi + (size_t)row * LL + j0 + u * 8);
    }
}

__global__ __launch_bounds__(256, 2) void attn_mma()
{
    extern __shared__ char smraw[];
    const uint32_t sb = (smem_u32(smraw) + 127) & ~127u;
    const uint32_t QHI = sb, QLO = sb + 16384, ST0 = sb + 32768;

    const int hb = blockIdx.y;
    const int h = hb >> 1, b = hb & 1;
    const int l0 = blockIdx.x * 128;
    const hf* qhi = g_qhi + (size_t)hb * LL * DK;
    const hf* qlo = g_qlo + (size_t)hb * LL * DK;
    const hf* khi = g_khi + (size_t)hb * LL * DK;
    const hf* klo = g_klo + (size_t)hb * LL * DK;
    const hf* vthi = g_vthi + (size_t)hb * DK * LL;

    const int t = threadIdx.x, w = t >> 5, l = t & 31;
    const int gid = l >> 2, tig = l & 3;
    const int mi = l >> 3;

    // Load Q tile (hi+lo) into smem
    #pragma unroll
    for (int i = 0; i < 4; ++i) {
        int g = i * 256 + t;
        int row = g >> 3, u = g & 7;
        uint32_t s = swz(row, u);
        *(uint4*)(smraw + (QHI - sb) + s) =
            *(const uint4*)(qhi + (size_t)(l0 + row) * DK + u * 8);
        *(uint4*)(smraw + (QLO - sb) + s) =
            *(const uint4*)(qlo + (size_t)(l0 + row) * DK + u * 8);
    }
    attn_fill(ST0, khi, klo, vthi, 0);
    CP_COMMIT();
    __syncthreads();

    uint32_t qfh[4][4];
    #pragma unroll
    for (int kt = 0; kt < 4; ++kt) {
        int row = w * 16 + (l & 7) + ((mi & 1) << 3);
        int u = kt * 2 + (mi >> 1);
        ldm4(qfh[kt], QHI + swz(row, u));
    }

    float o[8][4] = {};
    float m0 = -1e30f, m1 = -1e30f, l0s = 0.f, l1s = 0.f;

    for (int jt = 0; jt < 32; ++jt) {
        if (jt + 1 < 32) {
            attn_fill(ST0 + ((jt + 1) & 1) * ATTN_STAGE, khi, klo, vthi,
                      (jt + 1) * 64);
            CP_COMMIT();
            CP_WAIT1();
        } else {
            CP_WAIT0();
        }
        __syncthreads();
        const uint32_t tb = ST0 + (jt & 1) * ATTN_STAGE;

        // ---- S = Q K^T (3-MMA split) ----
        float s[8][4] = {};
        #pragma unroll
        for (int kt = 0; kt < 4; ++kt) {
            uint32_t qfl[4];
            {
                int row = w * 16 + (l & 7) + ((mi & 1) << 3);
                int u = kt * 2 + (mi >> 1);
                ldm4(qfl, QLO + swz(row, u));
            }
            uint32_t kh[8][2], kl[8][2];
            #pragma unroll
            for (int jp = 0; jp < 4; ++jp) {
                int row = jp * 16 + ((mi >> 1) << 3) + (l & 7);
                int u = kt * 2 + (mi & 1);
                uint32_t r4[4];
                ldm4(r4, tb + swz(row, u));
                kh[2*jp][0] = r4[0]; kh[2*jp][1] = r4[1];
                kh[2*jp+1][0] = r4[2]; kh[2*jp+1][1] = r4[3];
                ldm4(r4, tb + 8192 + swz(row, u));
                kl[2*jp][0] = r4[0]; kl[2*jp][1] = r4[1];
                kl[2*jp+1][0] = r4[2]; kl[2*jp+1][1] = r4[3];
            }
            #pragma unroll
            for (int n = 0; n < 8; ++n) {
                mma16816(s[n], qfh[kt], kh[n]);
                mma16816(s[n], qfh[kt], kl[n]);
                mma16816(s[n], qfl,     kh[n]);
            }
        }

        // ---- online softmax ----
        float rm0 = -1e30f, rm1 = -1e30f;
        #pragma unroll
        for (int n = 0; n < 8; ++n) {
            rm0 = fmaxf(rm0, fmaxf(s[n][0], s[n][1]));
            rm1 = fmaxf(rm1, fmaxf(s[n][2], s[n][3]));
        }
        rm0 = fmaxf(rm0, __shfl_xor_sync(0xffffffffu, rm0, 1));
        rm0 = fmaxf(rm0, __shfl_xor_sync(0xffffffffu, rm0, 2));
        rm1 = fmaxf(rm1, __shfl_xor_sync(0xffffffffu, rm1, 1));
        rm1 = fmaxf(rm1, __shfl_xor_sync(0xffffffffu, rm1, 2));
        const float mn0 = fmaxf(m0, rm0), mn1 = fmaxf(m1, rm1);
        const float sc0 = __expf(m0 - mn0), sc1 = __expf(m1 - mn1);
        m0 = mn0; m1 = mn1;
        float rs0 = 0.f, rs1 = 0.f;
        #pragma unroll
        for (int n = 0; n < 8; ++n) {
            s[n][0] = __expf(s[n][0] - mn0); s[n][1] = __expf(s[n][1] - mn0);
            s[n][2] = __expf(s[n][2] - mn1); s[n][3] = __expf(s[n][3] - mn1);
            rs0 += s[n][0] + s[n][1];
            rs1 += s[n][2] + s[n][3];
        }
        rs0 += __shfl_xor_sync(0xffffffffu, rs0, 1);
        rs0 += __shfl_xor_sync(0xffffffffu, rs0, 2);
        rs1 += __shfl_xor_sync(0xffffffffu, rs1, 1);
        rs1 += __shfl_xor_sync(0xffffffffu, rs1, 2);
        l0s = l0s * sc0 + rs0;
        l1s = l1s * sc1 + rs1;
        #pragma unroll
        for (int n = 0; n < 8; ++n) {
            o[n][0] *= sc0; o[n][1] *= sc0;
            o[n][2] *= sc1; o[n][3] *= sc1;
        }

        // ---- P (hi) x V (hi): 1 MMA ----
        #pragma unroll
        for (int kt = 0; kt < 4; ++kt) {
            uint32_t pah[4] = {
                pack_hf(s[2*kt][0],   s[2*kt][1]),
                pack_hf(s[2*kt][2],   s[2*kt][3]),
                pack_hf(s[2*kt+1][0], s[2*kt+1][1]),
                pack_hf(s[2*kt+1][2], s[2*kt+1][3]) };
            uint32_t vh[8][2];
            #pragma unroll
            for (int jp = 0; jp < 4; ++jp) {
                int row = jp * 16 + ((mi >> 1) << 3) + (l & 7);
                int u = kt * 2 + (mi & 1);
                uint32_t r4[4];
                ldm4(r4, tb + 16384 + swz(row, u));
                vh[2*jp][0] = r4[0]; vh[2*jp][1] = r4[1];
                vh[2*jp+1][0] = r4[2]; vh[2*jp+1][1] = r4[3];
            }
            #pragma unroll
            for (int n = 0; n < 8; ++n)
                mma16816(o[n], pah, vh[n]);
        }
        __syncthreads();
    }

    // ---- epilogue: (o / l) * q -> fp16 hi ----
    const float inv0 = 1.0f / l0s, inv1 = 1.0f / l1s;
    const size_t r0 = l0 + w * 16 + gid, r1 = r0 + 8;
    #pragma unroll
    for (int n = 0; n < 8; ++n) {
        const int d = 8 * n + 2 * tig;
        __half2 qh2a = *(const __half2*)(qhi + r0 * DK + d);
        __half2 ql2a = *(const __half2*)(qlo + r0 * DK + d);
        __half2 qh2b = *(const __half2*)(qhi + r1 * DK + d);
        __half2 ql2b = *(const __half2*)(qlo + r1 * DK + d);
        float qa0 = __half2float(qh2a.x) + __half2float(ql2a.x);
        float qa1 = __half2float(qh2a.y) + __half2float(ql2a.y);
        float qb0 = __half2float(qh2b.x) + __half2float(ql2b.x);
        float qb1 = __half2float(qh2b.y) + __half2float(ql2b.y);
        float v00 = o[n][0] * inv0 * qa0, v01 = o[n][1] * inv0 * qa1;
        float v10 = o[n][2] * inv1 * qb0, v11 = o[n][3] * inv1 * qb1;

        size_t o0 = ((size_t)b * LL + r0) * DM + h * DK + d;
        size_t o1 = ((size_t)b * LL + r1) * DM + h * DK + d;
        *(uint32_t*)(g_atthi + o0) = pack_hf(v00, v01);
        *(uint32_t*)(g_atthi + o1) = pack_hf(v10, v11);
    }
}

// ---------------------------------------------------------------------------
extern "C" void kernel_launch(void* const* d_in, const int* in_sizes, int n_in,
                              void* d_out, int out_size)
{
    const float* q  = (const float*)d_in[0];
    const float* k  = (const float*)d_in[1];
    const float* v  = (const float*)d_in[2];
    const float* wq = (const float*)d_in[3];
    const float* wk = (const float*)d_in[4];
    const float* wv = (const float*)d_in[5];
    const float* wp = (const float*)d_in[6];
    const float* bp = (const float*)d_in[7];
    float* out = (float*)d_out;

    cudaFuncSetAttribute(gemm_proj_mma,
                         cudaFuncAttributeMaxDynamicSharedMemorySize, GEMM_SMEM);
    cudaFuncSetAttribute(gemm_out_mma,
                         cudaFuncAttributeMaxDynamicSharedMemorySize, GEMM_SMEM);
    cudaFuncSetAttribute(attn_mma,
                         cudaFuncAttributeMaxDynamicSharedMemorySize, ATTN_SMEM);

    const int n4x = MROWS * DM / 4;
    conv_split_kernel<<<dim3((n4x + 255) / 256, 4), 256>>>(q, k, v, wp);
    conv_wt_kernel<<<dim3(NH, 3), 256>>>(wq, wk, wv);

    gemm_proj_mma<<<dim3(MROWS / 128, NH / 2, 3), 256, GEMM_SMEM>>>();

    attn_mma<<<dim3(LL / 128, NH * BB), 256, ATTN_SMEM>>>();

    gemm_out_mma<<<dim3(MROWS / 128, DM / 128), 256, GEMM_SMEM>>>(bp, out);
}